// round 11
// baseline (speedup 1.0000x reference)
#include <cuda_runtime.h>
#include <math.h>
#include <stdint.h>

#define BATCH 1024
#define NV    6890
#define NJ    24
#define NB    10
#define NP    207
#define KP    224          // 10 betas + 207 pose_feature + 7 pad
#define KA    28           // KP / 8 k-atoms
#define NCOL  20670        // V*3
#define NPAD  20736        // padded N (162 * 128)
#define NBLK  162          // NPAD / 128
#define MBLK  8            // BATCH / 128
#define NVB   54           // vert tiles of 128 (54*128 = 6912)
#define BTB   128          // batch tiles of 8
#define JCH   8            // jreg v-chunks per joint
#define CHSZ  862          // ceil(NV/JCH)

// ---------------- scratch (device globals) ----------------
__device__ float g_Bfrag[NBLK * KA * 16 * 32 * 2];   // tf32 B fragments (18.6 MB)
__device__ float g_Afrag[MBLK * KA * 8 * 32 * 4];    // tf32 A fragments (917 KB)
__device__ float g_vposed[BATCH * NPAD];             // v_posed minus template (84.9 MB)
__device__ float g_AB[BATCH * KP];                   // per-batch GEMM A rows
__device__ float g_A[BATCH * NJ * 12];               // per-batch skinning transforms (3x4)
__device__ float g_root[BATCH * 3];                  // root joint
__device__ float g_Jt[NJ * 3];
__device__ float g_Jsd[NJ * 3 * NB];
__device__ float g_Jpart[NJ * JCH * 33];             // jreg partials
// skinning tensor-core fragments (W: single tf32; A: hi/lo split)
__device__ uint4 g_Wfh[NVB * 3 * 8 * 32];
__device__ uint2 g_Afh[BTB * 3 * 12 * 32];
__device__ uint2 g_Afl[BTB * 3 * 12 * 32];

__constant__ int c_parents[NJ] = {-1,0,0,0,1,2,3,4,5,6,7,8,9,9,9,12,13,14,16,17,18,19,20,21};

#define OFF_VERTS 0
#define OFF_J     (BATCH * NCOL)
#define OFF_R     (OFF_J + BATCH * NJ * 3)
#define OFF_F     (OFF_R + BATCH * NJ * 9)

// ---------------- helpers ----------------
__device__ __forceinline__ uint32_t tf32_bits(float x) {
    uint32_t u;
    asm("cvt.rna.tf32.f32 %0, %1;" : "=r"(u) : "f"(x));
    return u;
}
__device__ __forceinline__ void mma_tf32(float4& d, uint4 a, uint2 b) {
    asm volatile(
        "mma.sync.aligned.m16n8k8.row.col.f32.tf32.tf32.f32 "
        "{%0,%1,%2,%3}, {%4,%5,%6,%7}, {%8,%9}, {%0,%1,%2,%3};"
        : "+f"(d.x), "+f"(d.y), "+f"(d.z), "+f"(d.w)
        : "r"(a.x), "r"(a.y), "r"(a.z), "r"(a.w), "r"(b.x), "r"(b.y));
}
typedef unsigned long long u64;
__device__ __forceinline__ u64 pack2(float x, float y) {
    u64 r; asm("mov.b64 %0, {%1, %2};" : "=l"(r) : "f"(x), "f"(y)); return r;
}
__device__ __forceinline__ u64 ffma2(u64 a, u64 b, u64 c) {
    u64 d; asm("fma.rn.f32x2 %0, %1, %2, %3;" : "=l"(d) : "l"(a), "l"(b), "l"(c)); return d;
}
__device__ __forceinline__ float2 unpack2(u64 v) {
    float2 f; asm("mov.b64 {%0, %1}, %2;" : "=f"(f.x), "=f"(f.y) : "l"(v)); return f;
}
__device__ __forceinline__ void split_tf32(float x, uint32_t& hi, uint32_t& lo) {
    hi = tf32_bits(x);
    lo = tf32_bits(x - __uint_as_float(hi));
}

// ============================================================================
// Kernel 1 (fused front):
//   blocks [0, NBLK*KA)        : tf32 B fragments for GEMM
//   blocks [+0, +162)          : W skin fragments (single tf32)
//   blocks [+162, +162+192)    : jreg partials (8 v-chunks per joint)
// ============================================================================
#define BFRAG_BLOCKS (NBLK * KA)
#define WFRAG_BLOCKS ((NVB * 3 * 8 * 32) / 256)
#define JREG_BLOCKS  (NJ * JCH)
__global__ void __launch_bounds__(256) k_front(const float* __restrict__ shapedirs,
                                               const float* __restrict__ posedirs,
                                               const float* __restrict__ wgt,
                                               const float* __restrict__ Jreg,
                                               const float* __restrict__ vtmpl) {
    __shared__ float smem_f[8 * 128];
    int tid = threadIdx.x;
    if (blockIdx.x < BFRAG_BLOCKS) {
        float (*sW8)[128] = (float (*)[128])smem_f;
        int n_blk = blockIdx.x % NBLK;
        int ka = blockIdx.x / NBLK;
#pragma unroll
        for (int r = 0; r < 4; r++) {
            int e = tid + r * 256;
            int kk = e >> 7;
            int nn = e & 127;
            int k = ka * 8 + kk;
            int n = n_blk * 128 + nn;
            float val = 0.f;
            if (n < NCOL) {
                if (k < NB)            val = shapedirs[n * NB + k];
                else if (k < NB + NP)  val = posedirs[(k - NB) * NCOL + n];
            }
            sW8[kk][nn] = val;
        }
        __syncthreads();
        float2* gB = (float2*)g_Bfrag;
#pragma unroll
        for (int r = 0; r < 2; r++) {
            int e = tid + r * 256;
            int n_sub = e >> 5;
            int t = e & 31;
            int g = t >> 2, tig = t & 3;
            float b0 = sW8[tig][n_sub * 8 + g];
            float b1 = sW8[tig + 4][n_sub * 8 + g];
            float2 v;
            v.x = __uint_as_float(tf32_bits(b0));
            v.y = __uint_as_float(tf32_bits(b1));
            gB[((size_t)(n_blk * KA + ka) * 16 + n_sub) * 32 + t] = v;
        }
    } else if (blockIdx.x < BFRAG_BLOCKS + WFRAG_BLOCKS) {
        // W skin fragments (single tf32)
        int idx = (blockIdx.x - BFRAG_BLOCKS) * 256 + tid;
        int lane = idx & 31;
        int atom = idx >> 5;
        int ma = atom & 7;
        int rest = atom >> 3;
        int ka = rest % 3;
        int vb = rest / 3;
        int g = lane >> 2, tig = lane & 3;
        int v0 = vb * 128 + ma * 16 + g;
        int j0 = ka * 8 + tig;
        float w00 = (v0     < NV) ? wgt[v0 * NJ + j0]           : 0.f;
        float w01 = (v0     < NV) ? wgt[v0 * NJ + j0 + 4]       : 0.f;
        float w10 = (v0 + 8 < NV) ? wgt[(v0 + 8) * NJ + j0]     : 0.f;
        float w11 = (v0 + 8 < NV) ? wgt[(v0 + 8) * NJ + j0 + 4] : 0.f;
        uint4 hi;
        hi.x = tf32_bits(w00);
        hi.y = tf32_bits(w10);
        hi.z = tf32_bits(w01);
        hi.w = tf32_bits(w11);
        g_Wfh[idx] = hi;
    } else {
        // jreg partials: joint j, chunk c
        int blk = blockIdx.x - BFRAG_BLOCKS - WFRAG_BLOCKS;
        int j = blk >> 3;
        int c = blk & 7;
        int vbeg = c * CHSZ;
        int vend = vbeg + CHSZ; if (vend > NV) vend = NV;
        float acc[33];
#pragma unroll
        for (int i = 0; i < 33; i++) acc[i] = 0.f;
        for (int v = vbeg + tid; v < vend; v += 256) {
            float r = Jreg[j * NV + v];
#pragma unroll
            for (int k = 0; k < 3; k++) {
                acc[k] = fmaf(r, vtmpl[v * 3 + k], acc[k]);
#pragma unroll
                for (int l = 0; l < NB; l++)
                    acc[3 + k * NB + l] = fmaf(r, shapedirs[(v * 3 + k) * NB + l], acc[3 + k * NB + l]);
            }
        }
        float (*part)[33] = (float (*)[33])smem_f;
        int lane = tid & 31, warp = tid >> 5;
#pragma unroll
        for (int i = 0; i < 33; i++) {
            float x = acc[i];
            for (int off = 16; off; off >>= 1) x += __shfl_down_sync(0xffffffffu, x, off);
            if (lane == 0) part[warp][i] = x;
        }
        __syncthreads();
        if (tid < 33) {
            float s = 0.f;
#pragma unroll
            for (int w = 0; w < 8; w++) s += part[w][tid];
            g_Jpart[blk * 33 + tid] = s;
        }
    }
}

// ============================================================================
// Kernel 1b: tiny jreg partial reduce (1 block).  792 outputs, 8 partials each.
// ============================================================================
__global__ void k_jred() {
    int tid = threadIdx.x;
    for (int i = tid; i < NJ * 33; i += 256) {
        int j = i / 33, e = i % 33;
        float s = 0.f;
#pragma unroll
        for (int c = 0; c < JCH; c++) s += g_Jpart[(j * JCH + c) * 33 + e];
        if (e < 3) g_Jt[j * 3 + e] = s;
        else       g_Jsd[j * 30 + (e - 3)] = s;
    }
}

// ============================================================================
// Kernel 2: per-batch rodrigues / chain / A matrices / outputs J & R (R10)
// ============================================================================
__global__ void k_batch(const float* __restrict__ pose,
                        const float* __restrict__ betas,
                        const float* __restrict__ gorient,
                        float* __restrict__ out) {
    int b = blockIdx.x;
    int t = threadIdx.x;
    __shared__ float sR[NJ][9];
    __shared__ float sJ[NJ][3];
    __shared__ float sG[NJ][12];

    if (t < NJ) {
        float rx, ry, rz;
        if (t == 0) { rx = gorient[b*3+0]; ry = gorient[b*3+1]; rz = gorient[b*3+2]; }
        else { const float* p = pose + b*69 + (t-1)*3; rx = p[0]; ry = p[1]; rz = p[2]; }
        float xa = rx + 1e-8f, ya = ry + 1e-8f, za = rz + 1e-8f;
        float angle = sqrtf(xa*xa + ya*ya + za*za);
        float inv = 1.f / angle;
        float ax = rx*inv, ay = ry*inv, az = rz*inv;
        float s = sinf(angle), c = cosf(angle);
        float K[9] = {0.f,-az,ay, az,0.f,-ax, -ay,ax,0.f};
        float R[9];
#pragma unroll
        for (int r = 0; r < 3; r++)
#pragma unroll
            for (int cc = 0; cc < 3; cc++) {
                float k2 = 0.f;
#pragma unroll
                for (int m = 0; m < 3; m++) k2 += K[r*3+m] * K[m*3+cc];
                R[r*3+cc] = (r==cc ? 1.f : 0.f) + s*K[r*3+cc] + (1.f - c)*k2;
            }
#pragma unroll
        for (int i = 0; i < 9; i++) sR[t][i] = R[i];
#pragma unroll
        for (int i = 0; i < 9; i++) out[OFF_R + (size_t)b*216 + t*9 + i] = R[i];
        if (t >= 1) {
#pragma unroll
            for (int i = 0; i < 9; i++) {
                float id = (i==0 || i==4 || i==8) ? 1.f : 0.f;
                g_AB[b*KP + NB + (t-1)*9 + i] = R[i] - id;
            }
        }
#pragma unroll
        for (int k = 0; k < 3; k++) {
            float jr = g_Jt[t*3 + k];
#pragma unroll
            for (int l = 0; l < NB; l++)
                jr = fmaf(betas[b*NB + l], g_Jsd[t*30 + k*NB + l], jr);
            sJ[t][k] = jr;
        }
    }
    if (t < NB) g_AB[b*KP + t] = betas[b*NB + t];
    if (t == 24) {
#pragma unroll
        for (int i = NB + NP; i < KP; i++) g_AB[b*KP + i] = 0.f;
    }
    __syncthreads();

    if (t == 0) {
#pragma unroll
        for (int r = 0; r < 3; r++) {
            sG[0][r*4+0] = sR[0][r*3+0];
            sG[0][r*4+1] = sR[0][r*3+1];
            sG[0][r*4+2] = sR[0][r*3+2];
            sG[0][r*4+3] = sJ[0][r];
        }
        for (int j = 1; j < NJ; j++) {
            int p = c_parents[j];
            float rel0 = sJ[j][0] - sJ[p][0];
            float rel1 = sJ[j][1] - sJ[p][1];
            float rel2 = sJ[j][2] - sJ[p][2];
#pragma unroll
            for (int r = 0; r < 3; r++) {
                float g0 = sG[p][r*4+0], g1 = sG[p][r*4+1], g2 = sG[p][r*4+2];
#pragma unroll
                for (int cc = 0; cc < 3; cc++)
                    sG[j][r*4+cc] = g0*sR[j][0*3+cc] + g1*sR[j][1*3+cc] + g2*sR[j][2*3+cc];
                sG[j][r*4+3] = g0*rel0 + g1*rel1 + g2*rel2 + sG[p][r*4+3];
            }
        }
        g_root[b*3+0] = sG[0][3];
        g_root[b*3+1] = sG[0][7];
        g_root[b*3+2] = sG[0][11];
    }
    __syncthreads();

    if (t < NJ) {
        float j0 = sJ[t][0], j1 = sJ[t][1], j2 = sJ[t][2];
#pragma unroll
        for (int r = 0; r < 3; r++) {
            float g0 = sG[t][r*4+0], g1 = sG[t][r*4+1], g2 = sG[t][r*4+2], gt = sG[t][r*4+3];
            float* A = &g_A[((size_t)b*NJ + t)*12 + r*4];
            A[0] = g0; A[1] = g1; A[2] = g2;
            A[3] = gt - (g0*j0 + g1*j1 + g2*j2);
            out[OFF_J + (size_t)b*72 + t*3 + r] = gt - sG[0][r*4+3];
        }
    }
}

// ============================================================================
// Kernel 3: pack GEMM A fragments + skin A-mat fragments (hi/lo) (R10)
// ============================================================================
#define PACKA_THREADS (MBLK * KA * 8 * 32)
#define PACKAM_THREADS (BTB * 3 * 12 * 32)
__global__ void __launch_bounds__(256) k_pack() {
    int gidx = blockIdx.x * 256 + threadIdx.x;
    if (gidx < PACKA_THREADS) {
        int idx = gidx;
        int t = idx & 31;
        int m_sub = (idx >> 5) & 7;
        int rest = idx >> 8;
        int ka = rest % KA;
        int m_blk = rest / KA;
        int g = t >> 2, tig = t & 3;
        int row0 = m_blk * 128 + m_sub * 16 + g;
        int k0 = ka * 8 + tig;
        uint4 a;
        a.x = tf32_bits(g_AB[row0 * KP + k0]);
        a.y = tf32_bits(g_AB[(row0 + 8) * KP + k0]);
        a.z = tf32_bits(g_AB[row0 * KP + k0 + 4]);
        a.w = tf32_bits(g_AB[(row0 + 8) * KP + k0 + 4]);
        ((uint4*)g_Afrag)[((size_t)(m_blk * KA + ka) * 8 + m_sub) * 32 + t] = a;
    } else {
        int idx = gidx - PACKA_THREADS;
        int lane = idx & 31;
        int atom = idx >> 5;
        int na = atom % 12;
        int rest = atom / 12;
        int ka = rest % 3;
        int bt = rest / 3;
        int g = lane >> 2, tig = lane & 3;
        int b = bt * 8 + g;
        int j0 = ka * 8 + tig;
        float a0 = g_A[((size_t)b * NJ + j0) * 12 + na];
        float a1 = g_A[((size_t)b * NJ + j0 + 4) * 12 + na];
        uint2 hi, lo;
        split_tf32(a0, hi.x, lo.x);
        split_tf32(a1, hi.y, lo.y);
        g_Afh[idx] = hi;
        g_Afl[idx] = lo;
    }
}

// ============================================================================
// Kernel 4: tf32 tensor-core GEMM (R7/R10)
// ============================================================================
__global__ void __launch_bounds__(256, 2) k_gemm() {
    __shared__ uint4 sA[2][8][32];
    __shared__ uint2 sB[2][16][32];
    int n_blk = blockIdx.x;
    int m_blk = blockIdx.y;
    int tid = threadIdx.x;
    int lane = tid & 31;
    int wid = tid >> 5;
    int wm = wid >> 1;
    int wn = wid & 1;

    const uint4* gA = (const uint4*)g_Afrag + (size_t)m_blk * KA * 256;
    const uint2* gB = (const uint2*)g_Bfrag + (size_t)n_blk * KA * 512;

    float4 acc[2][8];
#pragma unroll
    for (int i = 0; i < 2; i++)
#pragma unroll
        for (int j = 0; j < 8; j++) acc[i][j] = make_float4(0.f, 0.f, 0.f, 0.f);

    uint4 pa = gA[tid];
    uint2 pb0 = gB[tid];
    uint2 pb1 = gB[tid + 256];

    int a_ms = tid >> 5;
    int b_ns0 = tid >> 5;
    int b_ns1 = 8 + (tid >> 5);

    for (int ka = 0; ka < KA; ka++) {
        int buf = ka & 1;
        sA[buf][a_ms][lane] = pa;
        sB[buf][b_ns0][lane] = pb0;
        sB[buf][b_ns1][lane] = pb1;
        __syncthreads();
        if (ka + 1 < KA) {
            pa  = gA[(ka + 1) * 256 + tid];
            pb0 = gB[(ka + 1) * 512 + tid];
            pb1 = gB[(ka + 1) * 512 + tid + 256];
        }
        uint4 af[2];
        af[0] = sA[buf][wm * 2 + 0][lane];
        af[1] = sA[buf][wm * 2 + 1][lane];
        uint2 bf[8];
#pragma unroll
        for (int j = 0; j < 8; j++) bf[j] = sB[buf][wn * 8 + j][lane];
#pragma unroll
        for (int i = 0; i < 2; i++)
#pragma unroll
            for (int j = 0; j < 8; j++)
                mma_tf32(acc[i][j], af[i], bf[j]);
    }

    int g = lane >> 2, tig = lane & 3;
#pragma unroll
    for (int i = 0; i < 2; i++) {
        int r0 = m_blk * 128 + (wm * 2 + i) * 16 + g;
#pragma unroll
        for (int j = 0; j < 8; j++) {
            int c = n_blk * 128 + (wn * 8 + j) * 8 + tig * 2;
            *(float2*)&g_vposed[(size_t)r0 * NPAD + c] = make_float2(acc[i][j].x, acc[i][j].y);
            *(float2*)&g_vposed[(size_t)(r0 + 8) * NPAD + c] = make_float2(acc[i][j].z, acc[i][j].w);
        }
    }
}

// ============================================================================
// Kernel 5: tensor-core skinning (exactly R10 — the current best)
// ============================================================================
__global__ void __launch_bounds__(256, 3) k_skin_tc(const float* __restrict__ vtmpl,
                                                    float* __restrict__ out_verts) {
    __shared__ uint2 sAh[3 * 12 * 32];
    __shared__ uint2 sAl[3 * 12 * 32];
    __shared__ float sP[8][385];
    __shared__ float sRoot[8][3];
    int vb = blockIdx.x;
    int bt = blockIdx.y;
    int v0 = vb * 128;
    int b0 = bt * 8;
    int tid = threadIdx.x;

    {
        const uint2* gh = g_Afh + (size_t)bt * 1152;
        const uint2* gl = g_Afl + (size_t)bt * 1152;
#pragma unroll
        for (int r = 0; r < 5; r++) {
            int i = tid + r * 256;
            if (i < 1152) { sAh[i] = gh[i]; sAl[i] = gl[i]; }
        }
    }
#pragma unroll
    for (int k = 0; k < 12; k++) {
        int idx = tid + k * 256;
        int bi = idx / 384;
        int off = idx % 384;
        int gcol = v0 * 3 + off;
        float tpl = (gcol < NCOL) ? vtmpl[gcol] : 0.f;
        sP[bi][off] = g_vposed[(size_t)(b0 + bi) * NPAD + gcol] + tpl;
    }
    if (tid < 24) sRoot[tid / 3][tid % 3] = g_root[(b0 + tid / 3) * 3 + tid % 3];
    __syncthreads();

    int lane = tid & 31;
    int ma = tid >> 5;
    int g = lane >> 2, tig = lane & 3;

    float4 acc[12];
#pragma unroll
    for (int i = 0; i < 12; i++) acc[i] = make_float4(0.f, 0.f, 0.f, 0.f);

#pragma unroll
    for (int ka = 0; ka < 3; ka++) {
        uint4 wh = g_Wfh[(((size_t)vb * 3 + ka) * 8 + ma) * 32 + lane];
#pragma unroll
        for (int na = 0; na < 12; na++) {
            uint2 bh = sAh[(ka * 12 + na) * 32 + lane];
            uint2 bl = sAl[(ka * 12 + na) * 32 + lane];
            mma_tf32(acc[na], wh, bh);
            mma_tf32(acc[na], wh, bl);
        }
    }

    int vl0 = ma * 16 + g;
#pragma unroll
    for (int pp = 0; pp < 4; pp++) {
        int vl = vl0 + (pp >> 1) * 8;
        int bi = 2 * tig + (pp & 1);
        int v = v0 + vl;
        if (v < NV) {
            float T[12];
#pragma unroll
            for (int na = 0; na < 12; na++) {
                float4 a = acc[na];
                T[na] = (pp == 0) ? a.x : (pp == 1) ? a.y : (pp == 2) ? a.z : a.w;
            }
            float px = sP[bi][vl * 3 + 0];
            float py = sP[bi][vl * 3 + 1];
            float pz = sP[bi][vl * 3 + 2];
            float ox = T[0]*px + T[1]*py + T[2] *pz + T[3]  - sRoot[bi][0];
            float oy = T[4]*px + T[5]*py + T[6] *pz + T[7]  - sRoot[bi][1];
            float oz = T[8]*px + T[9]*py + T[10]*pz + T[11] - sRoot[bi][2];
            size_t o = (size_t)(b0 + bi) * NCOL + (size_t)v * 3;
            out_verts[o + 0] = ox;
            out_verts[o + 1] = oy;
            out_verts[o + 2] = oz;
        }
    }
}

// ============================================================================
// Kernel 6: jfv v2 — warp-per-batch, 8 batches/block, Jh chunk staged in smem.
// Cuts Jh L2 traffic 240 MB -> 60 MB.
// ============================================================================
#define JFV_VC 256
__global__ void __launch_bounds__(256) k_jfv(const float* __restrict__ verts,
                                             const float* __restrict__ Jh,
                                             float* __restrict__ out_jfv) {
    __shared__ float sJh[17][JFV_VC];
    int b = blockIdx.x * 8 + (threadIdx.x >> 5);
    int lane = threadIdx.x & 31;
    int tid = threadIdx.x;

    float acc[51];
#pragma unroll
    for (int i = 0; i < 51; i++) acc[i] = 0.f;

    const float* vb = verts + (size_t)b * NCOL;

    for (int vbase = 0; vbase < NV; vbase += JFV_VC) {
        // stage Jh chunk [17][JFV_VC]
        __syncthreads();
        for (int idx = tid; idx < 17 * JFV_VC; idx += 256) {
            int vv = idx & (JFV_VC - 1);
            int j = idx >> 8;
            int v = vbase + vv;
            sJh[j][vv] = (v < NV) ? Jh[j * NV + v] : 0.f;
        }
        __syncthreads();

#pragma unroll
        for (int i = 0; i < JFV_VC / 32; i++) {
            int vv = lane + 32 * i;
            int v = vbase + vv;
            float x = 0.f, y = 0.f, z = 0.f;
            if (v < NV) {
                x = vb[v * 3 + 0];
                y = vb[v * 3 + 1];
                z = vb[v * 3 + 2];
            }
#pragma unroll
            for (int j = 0; j < 17; j++) {
                float jr = sJh[j][vv];
                acc[j*3+0] = fmaf(jr, x, acc[j*3+0]);
                acc[j*3+1] = fmaf(jr, y, acc[j*3+1]);
                acc[j*3+2] = fmaf(jr, z, acc[j*3+2]);
            }
        }
    }

    // warp-reduce each of the 51 accumulators
#pragma unroll
    for (int i = 0; i < 51; i++) {
        float x = acc[i];
        for (int off = 16; off; off >>= 1) x += __shfl_down_sync(0xffffffffu, x, off);
        acc[i] = x;
    }
    if (lane == 0) {
        float r0 = acc[0], r1 = acc[1], r2 = acc[2];
#pragma unroll
        for (int jk = 0; jk < 51; jk++) {
            int k = jk % 3;
            float root = (k == 0) ? r0 : (k == 1) ? r1 : r2;
            out_jfv[(size_t)b * 51 + jk] = acc[jk] - root;
        }
    }
}

// ============================================================================
extern "C" void kernel_launch(void* const* d_in, const int* in_sizes, int n_in,
                              void* d_out, int out_size) {
    const float* pose      = (const float*)d_in[0];
    const float* betas     = (const float*)d_in[1];
    const float* gorient   = (const float*)d_in[2];
    const float* vtmpl     = (const float*)d_in[3];
    const float* shapedirs = (const float*)d_in[4];
    const float* posedirs  = (const float*)d_in[5];
    const float* Jreg      = (const float*)d_in[6];
    const float* Jh        = (const float*)d_in[7];
    const float* wgt       = (const float*)d_in[8];
    float* out = (float*)d_out;

    k_front<<<BFRAG_BLOCKS + WFRAG_BLOCKS + JREG_BLOCKS, 256>>>(shapedirs, posedirs, wgt, Jreg, vtmpl);
    k_jred<<<1, 256>>>();
    k_batch<<<BATCH, 32>>>(pose, betas, gorient, out);
    k_pack<<<(PACKA_THREADS + PACKAM_THREADS) / 256, 256>>>();
    k_gemm<<<dim3(NBLK, MBLK), 256>>>();
    k_skin_tc<<<dim3(NVB, BTB), 256>>>(vtmpl, out + OFF_VERTS);
    k_jfv<<<BATCH / 8, 256>>>(out + OFF_VERTS, Jh, out + OFF_F);
}

// round 12
// speedup vs baseline: 1.1770x; 1.1770x over previous
#include <cuda_runtime.h>
#include <math.h>
#include <stdint.h>

#define BATCH 1024
#define NV    6890
#define NJ    24
#define NB    10
#define NP    207
#define KP    224          // 10 betas + 207 pose_feature + 7 pad
#define KA    28           // KP / 8 k-atoms
#define NCOL  20670        // V*3
#define NPAD  20736        // padded N (162 * 128)
#define NBLK  162          // NPAD / 128
#define MBLK  8            // BATCH / 128
#define NVB   54           // vert tiles of 128 (54*128 = 6912)
#define BTB   128          // batch tiles of 8

// ---------------- scratch (device globals) ----------------
__device__ float g_Bfrag[NBLK * KA * 16 * 32 * 2];   // tf32 B fragments (18.6 MB)
__device__ float g_Afrag[MBLK * KA * 8 * 32 * 4];    // tf32 A fragments (917 KB)
__device__ float g_vposed[BATCH * NPAD];             // v_posed minus template (84.9 MB)
__device__ float g_AB[BATCH * KP];                   // per-batch GEMM A rows
__device__ float g_A[BATCH * NJ * 12];               // per-batch skinning transforms (3x4)
__device__ float g_root[BATCH * 3];                  // root joint
__device__ float g_Jt[NJ * 3];
__device__ float g_Jsd[NJ * 3 * NB];
// skinning tensor-core fragments (W: single tf32; A: hi/lo split)
__device__ uint4 g_Wfh[NVB * 3 * 8 * 32];
__device__ uint2 g_Afh[BTB * 3 * 12 * 32];
__device__ uint2 g_Afl[BTB * 3 * 12 * 32];

__constant__ int c_parents[NJ] = {-1,0,0,0,1,2,3,4,5,6,7,8,9,9,9,12,13,14,16,17,18,19,20,21};

#define OFF_VERTS 0
#define OFF_J     (BATCH * NCOL)
#define OFF_R     (OFF_J + BATCH * NJ * 3)
#define OFF_F     (OFF_R + BATCH * NJ * 9)

// ---------------- helpers ----------------
__device__ __forceinline__ uint32_t tf32_bits(float x) {
    uint32_t u;
    asm("cvt.rna.tf32.f32 %0, %1;" : "=r"(u) : "f"(x));
    return u;
}
__device__ __forceinline__ void mma_tf32(float4& d, uint4 a, uint2 b) {
    asm volatile(
        "mma.sync.aligned.m16n8k8.row.col.f32.tf32.tf32.f32 "
        "{%0,%1,%2,%3}, {%4,%5,%6,%7}, {%8,%9}, {%0,%1,%2,%3};"
        : "+f"(d.x), "+f"(d.y), "+f"(d.z), "+f"(d.w)
        : "r"(a.x), "r"(a.y), "r"(a.z), "r"(a.w), "r"(b.x), "r"(b.y));
}
typedef unsigned long long u64;
__device__ __forceinline__ u64 pack2(float x, float y) {
    u64 r; asm("mov.b64 %0, {%1, %2};" : "=l"(r) : "f"(x), "f"(y)); return r;
}
__device__ __forceinline__ u64 ffma2(u64 a, u64 b, u64 c) {
    u64 d; asm("fma.rn.f32x2 %0, %1, %2, %3;" : "=l"(d) : "l"(a), "l"(b), "l"(c)); return d;
}
__device__ __forceinline__ float2 unpack2(u64 v) {
    float2 f; asm("mov.b64 {%0, %1}, %2;" : "=f"(f.x), "=f"(f.y) : "l"(v)); return f;
}
__device__ __forceinline__ void split_tf32(float x, uint32_t& hi, uint32_t& lo) {
    hi = tf32_bits(x);
    lo = tf32_bits(x - __uint_as_float(hi));
}

// ============================================================================
// Kernel 1: factorized joint regressor (R10)
// ============================================================================
__global__ void k_jreg(const float* __restrict__ Jreg,
                       const float* __restrict__ vtmpl,
                       const float* __restrict__ shapedirs) {
    int j = blockIdx.x;
    int tid = threadIdx.x;
    float acc[33];
#pragma unroll
    for (int i = 0; i < 33; i++) acc[i] = 0.f;
    for (int v = tid; v < NV; v += 256) {
        float r = Jreg[j * NV + v];
#pragma unroll
        for (int k = 0; k < 3; k++) {
            acc[k] = fmaf(r, vtmpl[v * 3 + k], acc[k]);
#pragma unroll
            for (int l = 0; l < NB; l++)
                acc[3 + k * NB + l] = fmaf(r, shapedirs[(v * 3 + k) * NB + l], acc[3 + k * NB + l]);
        }
    }
    __shared__ float part[8][33];
    int lane = tid & 31, warp = tid >> 5;
#pragma unroll
    for (int i = 0; i < 33; i++) {
        float x = acc[i];
        for (int off = 16; off; off >>= 1) x += __shfl_down_sync(0xffffffffu, x, off);
        if (lane == 0) part[warp][i] = x;
    }
    __syncthreads();
    if (tid < 33) {
        float s = 0.f;
#pragma unroll
        for (int w = 0; w < 8; w++) s += part[w][tid];
        if (tid < 3) g_Jt[j * 3 + tid] = s;
        else         g_Jsd[j * 30 + (tid - 3)] = s;
    }
}

// ============================================================================
// Kernel 2: build B fragments for GEMM + W fragments (single tf32) (R10)
// ============================================================================
#define BFRAG_BLOCKS (NBLK * KA)
__global__ void __launch_bounds__(256) k_front(const float* __restrict__ shapedirs,
                                               const float* __restrict__ posedirs,
                                               const float* __restrict__ wgt) {
    int tid = threadIdx.x;
    if (blockIdx.x < BFRAG_BLOCKS) {
        __shared__ float sW8[8][128];
        int n_blk = blockIdx.x % NBLK;
        int ka = blockIdx.x / NBLK;
#pragma unroll
        for (int r = 0; r < 4; r++) {
            int e = tid + r * 256;
            int kk = e >> 7;
            int nn = e & 127;
            int k = ka * 8 + kk;
            int n = n_blk * 128 + nn;
            float val = 0.f;
            if (n < NCOL) {
                if (k < NB)            val = shapedirs[n * NB + k];
                else if (k < NB + NP)  val = posedirs[(k - NB) * NCOL + n];
            }
            sW8[kk][nn] = val;
        }
        __syncthreads();
        float2* gB = (float2*)g_Bfrag;
#pragma unroll
        for (int r = 0; r < 2; r++) {
            int e = tid + r * 256;
            int n_sub = e >> 5;
            int t = e & 31;
            int g = t >> 2, tig = t & 3;
            float b0 = sW8[tig][n_sub * 8 + g];
            float b1 = sW8[tig + 4][n_sub * 8 + g];
            float2 v;
            v.x = __uint_as_float(tf32_bits(b0));
            v.y = __uint_as_float(tf32_bits(b1));
            gB[((size_t)(n_blk * KA + ka) * 16 + n_sub) * 32 + t] = v;
        }
    } else {
        // W skin fragments (single tf32)
        int idx = (blockIdx.x - BFRAG_BLOCKS) * 256 + tid;
        int lane = idx & 31;
        int atom = idx >> 5;
        int ma = atom & 7;
        int rest = atom >> 3;
        int ka = rest % 3;
        int vb = rest / 3;
        int g = lane >> 2, tig = lane & 3;
        int v0 = vb * 128 + ma * 16 + g;
        int j0 = ka * 8 + tig;
        float w00 = (v0     < NV) ? wgt[v0 * NJ + j0]           : 0.f;
        float w01 = (v0     < NV) ? wgt[v0 * NJ + j0 + 4]       : 0.f;
        float w10 = (v0 + 8 < NV) ? wgt[(v0 + 8) * NJ + j0]     : 0.f;
        float w11 = (v0 + 8 < NV) ? wgt[(v0 + 8) * NJ + j0 + 4] : 0.f;
        uint4 hi;
        hi.x = tf32_bits(w00);
        hi.y = tf32_bits(w10);
        hi.z = tf32_bits(w01);
        hi.w = tf32_bits(w11);
        g_Wfh[idx] = hi;
    }
}

// ============================================================================
// Kernel 3: per-batch rodrigues / chain / A matrices / outputs J & R (R10)
// ============================================================================
__global__ void k_batch(const float* __restrict__ pose,
                        const float* __restrict__ betas,
                        const float* __restrict__ gorient,
                        float* __restrict__ out) {
    int b = blockIdx.x;
    int t = threadIdx.x;
    __shared__ float sR[NJ][9];
    __shared__ float sJ[NJ][3];
    __shared__ float sG[NJ][12];

    if (t < NJ) {
        float rx, ry, rz;
        if (t == 0) { rx = gorient[b*3+0]; ry = gorient[b*3+1]; rz = gorient[b*3+2]; }
        else { const float* p = pose + b*69 + (t-1)*3; rx = p[0]; ry = p[1]; rz = p[2]; }
        float xa = rx + 1e-8f, ya = ry + 1e-8f, za = rz + 1e-8f;
        float angle = sqrtf(xa*xa + ya*ya + za*za);
        float inv = 1.f / angle;
        float ax = rx*inv, ay = ry*inv, az = rz*inv;
        float s = sinf(angle), c = cosf(angle);
        float K[9] = {0.f,-az,ay, az,0.f,-ax, -ay,ax,0.f};
        float R[9];
#pragma unroll
        for (int r = 0; r < 3; r++)
#pragma unroll
            for (int cc = 0; cc < 3; cc++) {
                float k2 = 0.f;
#pragma unroll
                for (int m = 0; m < 3; m++) k2 += K[r*3+m] * K[m*3+cc];
                R[r*3+cc] = (r==cc ? 1.f : 0.f) + s*K[r*3+cc] + (1.f - c)*k2;
            }
#pragma unroll
        for (int i = 0; i < 9; i++) sR[t][i] = R[i];
#pragma unroll
        for (int i = 0; i < 9; i++) out[OFF_R + (size_t)b*216 + t*9 + i] = R[i];
        if (t >= 1) {
#pragma unroll
            for (int i = 0; i < 9; i++) {
                float id = (i==0 || i==4 || i==8) ? 1.f : 0.f;
                g_AB[b*KP + NB + (t-1)*9 + i] = R[i] - id;
            }
        }
#pragma unroll
        for (int k = 0; k < 3; k++) {
            float jr = g_Jt[t*3 + k];
#pragma unroll
            for (int l = 0; l < NB; l++)
                jr = fmaf(betas[b*NB + l], g_Jsd[t*30 + k*NB + l], jr);
            sJ[t][k] = jr;
        }
    }
    if (t < NB) g_AB[b*KP + t] = betas[b*NB + t];
    if (t == 24) {
#pragma unroll
        for (int i = NB + NP; i < KP; i++) g_AB[b*KP + i] = 0.f;
    }
    __syncthreads();

    if (t == 0) {
#pragma unroll
        for (int r = 0; r < 3; r++) {
            sG[0][r*4+0] = sR[0][r*3+0];
            sG[0][r*4+1] = sR[0][r*3+1];
            sG[0][r*4+2] = sR[0][r*3+2];
            sG[0][r*4+3] = sJ[0][r];
        }
        for (int j = 1; j < NJ; j++) {
            int p = c_parents[j];
            float rel0 = sJ[j][0] - sJ[p][0];
            float rel1 = sJ[j][1] - sJ[p][1];
            float rel2 = sJ[j][2] - sJ[p][2];
#pragma unroll
            for (int r = 0; r < 3; r++) {
                float g0 = sG[p][r*4+0], g1 = sG[p][r*4+1], g2 = sG[p][r*4+2];
#pragma unroll
                for (int cc = 0; cc < 3; cc++)
                    sG[j][r*4+cc] = g0*sR[j][0*3+cc] + g1*sR[j][1*3+cc] + g2*sR[j][2*3+cc];
                sG[j][r*4+3] = g0*rel0 + g1*rel1 + g2*rel2 + sG[p][r*4+3];
            }
        }
        g_root[b*3+0] = sG[0][3];
        g_root[b*3+1] = sG[0][7];
        g_root[b*3+2] = sG[0][11];
    }
    __syncthreads();

    if (t < NJ) {
        float j0 = sJ[t][0], j1 = sJ[t][1], j2 = sJ[t][2];
#pragma unroll
        for (int r = 0; r < 3; r++) {
            float g0 = sG[t][r*4+0], g1 = sG[t][r*4+1], g2 = sG[t][r*4+2], gt = sG[t][r*4+3];
            float* A = &g_A[((size_t)b*NJ + t)*12 + r*4];
            A[0] = g0; A[1] = g1; A[2] = g2;
            A[3] = gt - (g0*j0 + g1*j1 + g2*j2);
            out[OFF_J + (size_t)b*72 + t*3 + r] = gt - sG[0][r*4+3];
        }
    }
}

// ============================================================================
// Kernel 4: pack GEMM A fragments + skin A-mat fragments (hi/lo) (R10)
// ============================================================================
#define PACKA_THREADS (MBLK * KA * 8 * 32)
#define PACKAM_THREADS (BTB * 3 * 12 * 32)
__global__ void __launch_bounds__(256) k_pack() {
    int gidx = blockIdx.x * 256 + threadIdx.x;
    if (gidx < PACKA_THREADS) {
        int idx = gidx;
        int t = idx & 31;
        int m_sub = (idx >> 5) & 7;
        int rest = idx >> 8;
        int ka = rest % KA;
        int m_blk = rest / KA;
        int g = t >> 2, tig = t & 3;
        int row0 = m_blk * 128 + m_sub * 16 + g;
        int k0 = ka * 8 + tig;
        uint4 a;
        a.x = tf32_bits(g_AB[row0 * KP + k0]);
        a.y = tf32_bits(g_AB[(row0 + 8) * KP + k0]);
        a.z = tf32_bits(g_AB[row0 * KP + k0 + 4]);
        a.w = tf32_bits(g_AB[(row0 + 8) * KP + k0 + 4]);
        ((uint4*)g_Afrag)[((size_t)(m_blk * KA + ka) * 8 + m_sub) * 32 + t] = a;
    } else {
        int idx = gidx - PACKA_THREADS;
        int lane = idx & 31;
        int atom = idx >> 5;
        int na = atom % 12;
        int rest = atom / 12;
        int ka = rest % 3;
        int bt = rest / 3;
        int g = lane >> 2, tig = lane & 3;
        int b = bt * 8 + g;
        int j0 = ka * 8 + tig;
        float a0 = g_A[((size_t)b * NJ + j0) * 12 + na];
        float a1 = g_A[((size_t)b * NJ + j0 + 4) * 12 + na];
        uint2 hi, lo;
        split_tf32(a0, hi.x, lo.x);
        split_tf32(a1, hi.y, lo.y);
        g_Afh[idx] = hi;
        g_Afl[idx] = lo;
    }
}

// ============================================================================
// Kernel 5: tf32 tensor-core GEMM v2 — 2 k-atoms per staging iteration.
// Halves __syncthreads count (28 -> 14) and doubles MMA ILP per phase;
// the loop was latency-bound (1430 cyc/iter at occ=2 blocks/SM).
// ============================================================================
__global__ void __launch_bounds__(256, 2) k_gemm() {
    __shared__ uint4 sA[2][2][8][32];    // [buf][atom][m_sub][t]  16 KB
    __shared__ uint2 sB[2][2][16][32];   // [buf][atom][n_sub][t]  16 KB
    int n_blk = blockIdx.x;
    int m_blk = blockIdx.y;
    int tid = threadIdx.x;
    int lane = tid & 31;
    int wid = tid >> 5;
    int wm = wid >> 1;
    int wn = wid & 1;

    const uint4* gA = (const uint4*)g_Afrag + (size_t)m_blk * KA * 256;
    const uint2* gB = (const uint2*)g_Bfrag + (size_t)n_blk * KA * 512;

    float4 acc[2][8];
#pragma unroll
    for (int i = 0; i < 2; i++)
#pragma unroll
        for (int j = 0; j < 8; j++) acc[i][j] = make_float4(0.f, 0.f, 0.f, 0.f);

    // prefetch stage 0 (atoms 0,1)
    uint4 pa[2];
    uint2 pb0[2], pb1[2];
#pragma unroll
    for (int u = 0; u < 2; u++) {
        pa[u]  = gA[u * 256 + tid];
        pb0[u] = gB[u * 512 + tid];
        pb1[u] = gB[u * 512 + tid + 256];
    }

    int a_ms = tid >> 5;
    int b_ns0 = tid >> 5;
    int b_ns1 = 8 + (tid >> 5);

#pragma unroll
    for (int s = 0; s < KA / 2; s++) {
        int buf = s & 1;
#pragma unroll
        for (int u = 0; u < 2; u++) {
            sA[buf][u][a_ms][lane] = pa[u];
            sB[buf][u][b_ns0][lane] = pb0[u];
            sB[buf][u][b_ns1][lane] = pb1[u];
        }
        __syncthreads();
        if (s + 1 < KA / 2) {
#pragma unroll
            for (int u = 0; u < 2; u++) {
                int ka = 2 * (s + 1) + u;
                pa[u]  = gA[ka * 256 + tid];
                pb0[u] = gB[ka * 512 + tid];
                pb1[u] = gB[ka * 512 + tid + 256];
            }
        }
#pragma unroll
        for (int u = 0; u < 2; u++) {
            uint4 af[2];
            af[0] = sA[buf][u][wm * 2 + 0][lane];
            af[1] = sA[buf][u][wm * 2 + 1][lane];
            uint2 bf[8];
#pragma unroll
            for (int j = 0; j < 8; j++) bf[j] = sB[buf][u][wn * 8 + j][lane];
#pragma unroll
            for (int i = 0; i < 2; i++)
#pragma unroll
                for (int j = 0; j < 8; j++)
                    mma_tf32(acc[i][j], af[i], bf[j]);
        }
    }

    int g = lane >> 2, tig = lane & 3;
#pragma unroll
    for (int i = 0; i < 2; i++) {
        int r0 = m_blk * 128 + (wm * 2 + i) * 16 + g;
#pragma unroll
        for (int j = 0; j < 8; j++) {
            int c = n_blk * 128 + (wn * 8 + j) * 8 + tig * 2;
            *(float2*)&g_vposed[(size_t)r0 * NPAD + c] = make_float2(acc[i][j].x, acc[i][j].y);
            *(float2*)&g_vposed[(size_t)(r0 + 8) * NPAD + c] = make_float2(acc[i][j].z, acc[i][j].w);
        }
    }
}

// ============================================================================
// Kernel 6: tensor-core skinning (exactly R10)
// ============================================================================
__global__ void __launch_bounds__(256, 3) k_skin_tc(const float* __restrict__ vtmpl,
                                                    float* __restrict__ out_verts) {
    __shared__ uint2 sAh[3 * 12 * 32];
    __shared__ uint2 sAl[3 * 12 * 32];
    __shared__ float sP[8][385];
    __shared__ float sRoot[8][3];
    int vb = blockIdx.x;
    int bt = blockIdx.y;
    int v0 = vb * 128;
    int b0 = bt * 8;
    int tid = threadIdx.x;

    {
        const uint2* gh = g_Afh + (size_t)bt * 1152;
        const uint2* gl = g_Afl + (size_t)bt * 1152;
#pragma unroll
        for (int r = 0; r < 5; r++) {
            int i = tid + r * 256;
            if (i < 1152) { sAh[i] = gh[i]; sAl[i] = gl[i]; }
        }
    }
#pragma unroll
    for (int k = 0; k < 12; k++) {
        int idx = tid + k * 256;
        int bi = idx / 384;
        int off = idx % 384;
        int gcol = v0 * 3 + off;
        float tpl = (gcol < NCOL) ? vtmpl[gcol] : 0.f;
        sP[bi][off] = g_vposed[(size_t)(b0 + bi) * NPAD + gcol] + tpl;
    }
    if (tid < 24) sRoot[tid / 3][tid % 3] = g_root[(b0 + tid / 3) * 3 + tid % 3];
    __syncthreads();

    int lane = tid & 31;
    int ma = tid >> 5;
    int g = lane >> 2, tig = lane & 3;

    float4 acc[12];
#pragma unroll
    for (int i = 0; i < 12; i++) acc[i] = make_float4(0.f, 0.f, 0.f, 0.f);

#pragma unroll
    for (int ka = 0; ka < 3; ka++) {
        uint4 wh = g_Wfh[(((size_t)vb * 3 + ka) * 8 + ma) * 32 + lane];
#pragma unroll
        for (int na = 0; na < 12; na++) {
            uint2 bh = sAh[(ka * 12 + na) * 32 + lane];
            uint2 bl = sAl[(ka * 12 + na) * 32 + lane];
            mma_tf32(acc[na], wh, bh);
            mma_tf32(acc[na], wh, bl);
        }
    }

    int vl0 = ma * 16 + g;
#pragma unroll
    for (int pp = 0; pp < 4; pp++) {
        int vl = vl0 + (pp >> 1) * 8;
        int bi = 2 * tig + (pp & 1);
        int v = v0 + vl;
        if (v < NV) {
            float T[12];
#pragma unroll
            for (int na = 0; na < 12; na++) {
                float4 a = acc[na];
                T[na] = (pp == 0) ? a.x : (pp == 1) ? a.y : (pp == 2) ? a.z : a.w;
            }
            float px = sP[bi][vl * 3 + 0];
            float py = sP[bi][vl * 3 + 1];
            float pz = sP[bi][vl * 3 + 2];
            float ox = T[0]*px + T[1]*py + T[2] *pz + T[3]  - sRoot[bi][0];
            float oy = T[4]*px + T[5]*py + T[6] *pz + T[7]  - sRoot[bi][1];
            float oz = T[8]*px + T[9]*py + T[10]*pz + T[11] - sRoot[bi][2];
            size_t o = (size_t)(b0 + bi) * NCOL + (size_t)v * 3;
            out_verts[o + 0] = ox;
            out_verts[o + 1] = oy;
            out_verts[o + 2] = oz;
        }
    }
}

// ============================================================================
// Kernel 7: jfv (exactly R10) — 2 batches / block, f32x2 packed.
// ============================================================================
__global__ void __launch_bounds__(256) k_jfv(const float* __restrict__ verts,
                                             const float* __restrict__ Jh,
                                             float* __restrict__ out_jfv) {
    int b0 = blockIdx.x * 2;
    int tid = threadIdx.x;
    u64 acc2[51];
#pragma unroll
    for (int i = 0; i < 51; i++) acc2[i] = 0ull;

    const float* va_base = verts + (size_t)b0 * NCOL;
    const float* vb_base = va_base + NCOL;
    for (int v = tid; v < NV; v += 256) {
        const float* va = va_base + (size_t)v * 3;
        const float* vb = vb_base + (size_t)v * 3;
        u64 x2 = pack2(va[0], vb[0]);
        u64 y2 = pack2(va[1], vb[1]);
        u64 z2 = pack2(va[2], vb[2]);
#pragma unroll
        for (int j = 0; j < 17; j++) {
            float jr = Jh[j * NV + v];
            u64 jr2 = pack2(jr, jr);
            acc2[j*3+0] = ffma2(jr2, x2, acc2[j*3+0]);
            acc2[j*3+1] = ffma2(jr2, y2, acc2[j*3+1]);
            acc2[j*3+2] = ffma2(jr2, z2, acc2[j*3+2]);
        }
    }

    float a[102];
#pragma unroll
    for (int i = 0; i < 51; i++) {
        float2 f = unpack2(acc2[i]);
        a[i] = f.x;
        a[51 + i] = f.y;
    }

    __shared__ float red[8][102];
    int lane = tid & 31, warp = tid >> 5;
#pragma unroll
    for (int i = 0; i < 102; i++) {
        float x = a[i];
        for (int off = 16; off; off >>= 1) x += __shfl_down_sync(0xffffffffu, x, off);
        if (lane == 0) red[warp][i] = x;
    }
    __syncthreads();
    if (tid < 102) {
        float s = 0.f;
#pragma unroll
        for (int w = 0; w < 8; w++) s += red[w][tid];
        red[0][tid] = s;
    }
    __syncthreads();
    if (tid < 102) {
        int bb = tid / 51;
        int jk = tid % 51;
        int k = jk % 3;
        float val = red[0][tid] - red[0][bb * 51 + k];
        out_jfv[(size_t)(b0 + bb) * 51 + jk] = val;
    }
}

// ============================================================================
extern "C" void kernel_launch(void* const* d_in, const int* in_sizes, int n_in,
                              void* d_out, int out_size) {
    const float* pose      = (const float*)d_in[0];
    const float* betas     = (const float*)d_in[1];
    const float* gorient   = (const float*)d_in[2];
    const float* vtmpl     = (const float*)d_in[3];
    const float* shapedirs = (const float*)d_in[4];
    const float* posedirs  = (const float*)d_in[5];
    const float* Jreg      = (const float*)d_in[6];
    const float* Jh        = (const float*)d_in[7];
    const float* wgt       = (const float*)d_in[8];
    float* out = (float*)d_out;

    k_jreg<<<NJ, 256>>>(Jreg, vtmpl, shapedirs);
    k_front<<<BFRAG_BLOCKS + (NVB * 3 * 8 * 32) / 256, 256>>>(shapedirs, posedirs, wgt);
    k_batch<<<BATCH, 32>>>(pose, betas, gorient, out);
    k_pack<<<(PACKA_THREADS + PACKAM_THREADS) / 256, 256>>>();
    k_gemm<<<dim3(NBLK, MBLK), 256>>>();
    k_skin_tc<<<dim3(NVB, BTB), 256>>>(vtmpl, out + OFF_VERTS);
    k_jfv<<<BATCH / 2, 256>>>(out + OFF_VERTS, Jh, out + OFF_F);
}

// round 13
// speedup vs baseline: 1.3070x; 1.1104x over previous
#include <cuda_runtime.h>
#include <cuda_bf16.h>
#include <math.h>
#include <stdint.h>

#define BATCH 1024
#define NV    6890
#define NJ    24
#define NB    10
#define NP    207
#define KP    224          // 10 betas + 207 pose_feature + 7 pad
#define KA    28           // KP / 8 k-atoms
#define NCOL  20670        // V*3
#define NPAD  20736        // padded N (162 * 128)
#define NBLK  162          // NPAD / 128
#define MBLK  8            // BATCH / 128
#define NVB   54           // vert tiles of 128 (54*128 = 6912)
#define BTB   128          // batch tiles of 8
#define JCH   8            // jreg v-chunks per joint
#define CHSZ  862          // ceil(NV/JCH)

// ---------------- scratch (device globals) ----------------
__device__ float g_Bfrag[NBLK * KA * 16 * 32 * 2];   // tf32 B fragments (18.6 MB)
__device__ float g_Afrag[MBLK * KA * 8 * 32 * 4];    // tf32 A fragments (917 KB)
__device__ __nv_bfloat16 g_vposed[BATCH * NPAD];     // v_posed minus template (42.5 MB, bf16)
__device__ float g_AB[BATCH * KP];                   // per-batch GEMM A rows
__device__ float g_A[BATCH * NJ * 12];               // per-batch skinning transforms (3x4)
__device__ float g_root[BATCH * 3];                  // root joint
__device__ float g_Jt[NJ * 3];
__device__ float g_Jsd[NJ * 3 * NB];
__device__ float g_Jpart[NJ * JCH * 33];             // jreg partials
// skinning tensor-core fragments (W: single tf32; A: hi/lo split)
__device__ uint4 g_Wfh[NVB * 3 * 8 * 32];
__device__ uint2 g_Afh[BTB * 3 * 12 * 32];
__device__ uint2 g_Afl[BTB * 3 * 12 * 32];

__constant__ int c_parents[NJ] = {-1,0,0,0,1,2,3,4,5,6,7,8,9,9,9,12,13,14,16,17,18,19,20,21};

#define OFF_VERTS 0
#define OFF_J     (BATCH * NCOL)
#define OFF_R     (OFF_J + BATCH * NJ * 3)
#define OFF_F     (OFF_R + BATCH * NJ * 9)

// ---------------- helpers ----------------
__device__ __forceinline__ uint32_t tf32_bits(float x) {
    uint32_t u;
    asm("cvt.rna.tf32.f32 %0, %1;" : "=r"(u) : "f"(x));
    return u;
}
__device__ __forceinline__ void mma_tf32(float4& d, uint4 a, uint2 b) {
    asm volatile(
        "mma.sync.aligned.m16n8k8.row.col.f32.tf32.tf32.f32 "
        "{%0,%1,%2,%3}, {%4,%5,%6,%7}, {%8,%9}, {%0,%1,%2,%3};"
        : "+f"(d.x), "+f"(d.y), "+f"(d.z), "+f"(d.w)
        : "r"(a.x), "r"(a.y), "r"(a.z), "r"(a.w), "r"(b.x), "r"(b.y));
}
// pack (lo, hi) floats into bf16x2 word: low 16 bits = lo
__device__ __forceinline__ uint32_t bf16x2_pack(float lo, float hi) {
    uint32_t d;
    asm("cvt.rn.bf16x2.f32 %0, %1, %2;" : "=r"(d) : "f"(hi), "f"(lo));
    return d;
}
typedef unsigned long long u64;
__device__ __forceinline__ u64 pack2(float x, float y) {
    u64 r; asm("mov.b64 %0, {%1, %2};" : "=l"(r) : "f"(x), "f"(y)); return r;
}
__device__ __forceinline__ u64 ffma2(u64 a, u64 b, u64 c) {
    u64 d; asm("fma.rn.f32x2 %0, %1, %2, %3;" : "=l"(d) : "l"(a), "l"(b), "l"(c)); return d;
}
__device__ __forceinline__ float2 unpack2(u64 v) {
    float2 f; asm("mov.b64 {%0, %1}, %2;" : "=f"(f.x), "=f"(f.y) : "l"(v)); return f;
}
__device__ __forceinline__ void split_tf32(float x, uint32_t& hi, uint32_t& lo) {
    hi = tf32_bits(x);
    lo = tf32_bits(x - __uint_as_float(hi));
}

// ============================================================================
// Kernel 1a: jreg partials — 8 v-chunks per joint, 192 blocks (standalone,
// NOT fused into k_front: the fused variant's tail imbalance regressed twice)
// ============================================================================
__global__ void __launch_bounds__(256) k_jreg_part(const float* __restrict__ Jreg,
                                                   const float* __restrict__ vtmpl,
                                                   const float* __restrict__ shapedirs) {
    int j = blockIdx.x >> 3;
    int c = blockIdx.x & 7;
    int tid = threadIdx.x;
    int vbeg = c * CHSZ;
    int vend = vbeg + CHSZ; if (vend > NV) vend = NV;
    float acc[33];
#pragma unroll
    for (int i = 0; i < 33; i++) acc[i] = 0.f;
    for (int v = vbeg + tid; v < vend; v += 256) {
        float r = Jreg[j * NV + v];
#pragma unroll
        for (int k = 0; k < 3; k++) {
            acc[k] = fmaf(r, vtmpl[v * 3 + k], acc[k]);
#pragma unroll
            for (int l = 0; l < NB; l++)
                acc[3 + k * NB + l] = fmaf(r, shapedirs[(v * 3 + k) * NB + l], acc[3 + k * NB + l]);
        }
    }
    __shared__ float part[8][33];
    int lane = tid & 31, warp = tid >> 5;
#pragma unroll
    for (int i = 0; i < 33; i++) {
        float x = acc[i];
        for (int off = 16; off; off >>= 1) x += __shfl_down_sync(0xffffffffu, x, off);
        if (lane == 0) part[warp][i] = x;
    }
    __syncthreads();
    if (tid < 33) {
        float s = 0.f;
#pragma unroll
        for (int w = 0; w < 8; w++) s += part[w][tid];
        g_Jpart[blockIdx.x * 33 + tid] = s;
    }
}

// ============================================================================
// Kernel 1b: tiny jreg reduce (1 block)
// ============================================================================
__global__ void k_jred() {
    int tid = threadIdx.x;
    for (int i = tid; i < NJ * 33; i += 256) {
        int j = i / 33, e = i % 33;
        float s = 0.f;
#pragma unroll
        for (int c = 0; c < JCH; c++) s += g_Jpart[(j * JCH + c) * 33 + e];
        if (e < 3) g_Jt[j * 3 + e] = s;
        else       g_Jsd[j * 30 + (e - 3)] = s;
    }
}

// ============================================================================
// Kernel 2: build B fragments for GEMM + W fragments (single tf32) (R12)
// ============================================================================
#define BFRAG_BLOCKS (NBLK * KA)
__global__ void __launch_bounds__(256) k_front(const float* __restrict__ shapedirs,
                                               const float* __restrict__ posedirs,
                                               const float* __restrict__ wgt) {
    int tid = threadIdx.x;
    if (blockIdx.x < BFRAG_BLOCKS) {
        __shared__ float sW8[8][128];
        int n_blk = blockIdx.x % NBLK;
        int ka = blockIdx.x / NBLK;
#pragma unroll
        for (int r = 0; r < 4; r++) {
            int e = tid + r * 256;
            int kk = e >> 7;
            int nn = e & 127;
            int k = ka * 8 + kk;
            int n = n_blk * 128 + nn;
            float val = 0.f;
            if (n < NCOL) {
                if (k < NB)            val = shapedirs[n * NB + k];
                else if (k < NB + NP)  val = posedirs[(k - NB) * NCOL + n];
            }
            sW8[kk][nn] = val;
        }
        __syncthreads();
        float2* gB = (float2*)g_Bfrag;
#pragma unroll
        for (int r = 0; r < 2; r++) {
            int e = tid + r * 256;
            int n_sub = e >> 5;
            int t = e & 31;
            int g = t >> 2, tig = t & 3;
            float b0 = sW8[tig][n_sub * 8 + g];
            float b1 = sW8[tig + 4][n_sub * 8 + g];
            float2 v;
            v.x = __uint_as_float(tf32_bits(b0));
            v.y = __uint_as_float(tf32_bits(b1));
            gB[((size_t)(n_blk * KA + ka) * 16 + n_sub) * 32 + t] = v;
        }
    } else {
        // W skin fragments (single tf32)
        int idx = (blockIdx.x - BFRAG_BLOCKS) * 256 + tid;
        int lane = idx & 31;
        int atom = idx >> 5;
        int ma = atom & 7;
        int rest = atom >> 3;
        int ka = rest % 3;
        int vb = rest / 3;
        int g = lane >> 2, tig = lane & 3;
        int v0 = vb * 128 + ma * 16 + g;
        int j0 = ka * 8 + tig;
        float w00 = (v0     < NV) ? wgt[v0 * NJ + j0]           : 0.f;
        float w01 = (v0     < NV) ? wgt[v0 * NJ + j0 + 4]       : 0.f;
        float w10 = (v0 + 8 < NV) ? wgt[(v0 + 8) * NJ + j0]     : 0.f;
        float w11 = (v0 + 8 < NV) ? wgt[(v0 + 8) * NJ + j0 + 4] : 0.f;
        uint4 hi;
        hi.x = tf32_bits(w00);
        hi.y = tf32_bits(w10);
        hi.z = tf32_bits(w01);
        hi.w = tf32_bits(w11);
        g_Wfh[idx] = hi;
    }
}

// ============================================================================
// Kernel 3: per-batch rodrigues / chain / A matrices / outputs J & R (R12)
// ============================================================================
__global__ void k_batch(const float* __restrict__ pose,
                        const float* __restrict__ betas,
                        const float* __restrict__ gorient,
                        float* __restrict__ out) {
    int b = blockIdx.x;
    int t = threadIdx.x;
    __shared__ float sR[NJ][9];
    __shared__ float sJ[NJ][3];
    __shared__ float sG[NJ][12];

    if (t < NJ) {
        float rx, ry, rz;
        if (t == 0) { rx = gorient[b*3+0]; ry = gorient[b*3+1]; rz = gorient[b*3+2]; }
        else { const float* p = pose + b*69 + (t-1)*3; rx = p[0]; ry = p[1]; rz = p[2]; }
        float xa = rx + 1e-8f, ya = ry + 1e-8f, za = rz + 1e-8f;
        float angle = sqrtf(xa*xa + ya*ya + za*za);
        float inv = 1.f / angle;
        float ax = rx*inv, ay = ry*inv, az = rz*inv;
        float s = sinf(angle), c = cosf(angle);
        float K[9] = {0.f,-az,ay, az,0.f,-ax, -ay,ax,0.f};
        float R[9];
#pragma unroll
        for (int r = 0; r < 3; r++)
#pragma unroll
            for (int cc = 0; cc < 3; cc++) {
                float k2 = 0.f;
#pragma unroll
                for (int m = 0; m < 3; m++) k2 += K[r*3+m] * K[m*3+cc];
                R[r*3+cc] = (r==cc ? 1.f : 0.f) + s*K[r*3+cc] + (1.f - c)*k2;
            }
#pragma unroll
        for (int i = 0; i < 9; i++) sR[t][i] = R[i];
#pragma unroll
        for (int i = 0; i < 9; i++) out[OFF_R + (size_t)b*216 + t*9 + i] = R[i];
        if (t >= 1) {
#pragma unroll
            for (int i = 0; i < 9; i++) {
                float id = (i==0 || i==4 || i==8) ? 1.f : 0.f;
                g_AB[b*KP + NB + (t-1)*9 + i] = R[i] - id;
            }
        }
#pragma unroll
        for (int k = 0; k < 3; k++) {
            float jr = g_Jt[t*3 + k];
#pragma unroll
            for (int l = 0; l < NB; l++)
                jr = fmaf(betas[b*NB + l], g_Jsd[t*30 + k*NB + l], jr);
            sJ[t][k] = jr;
        }
    }
    if (t < NB) g_AB[b*KP + t] = betas[b*NB + t];
    if (t == 24) {
#pragma unroll
        for (int i = NB + NP; i < KP; i++) g_AB[b*KP + i] = 0.f;
    }
    __syncthreads();

    if (t == 0) {
#pragma unroll
        for (int r = 0; r < 3; r++) {
            sG[0][r*4+0] = sR[0][r*3+0];
            sG[0][r*4+1] = sR[0][r*3+1];
            sG[0][r*4+2] = sR[0][r*3+2];
            sG[0][r*4+3] = sJ[0][r];
        }
        for (int j = 1; j < NJ; j++) {
            int p = c_parents[j];
            float rel0 = sJ[j][0] - sJ[p][0];
            float rel1 = sJ[j][1] - sJ[p][1];
            float rel2 = sJ[j][2] - sJ[p][2];
#pragma unroll
            for (int r = 0; r < 3; r++) {
                float g0 = sG[p][r*4+0], g1 = sG[p][r*4+1], g2 = sG[p][r*4+2];
#pragma unroll
                for (int cc = 0; cc < 3; cc++)
                    sG[j][r*4+cc] = g0*sR[j][0*3+cc] + g1*sR[j][1*3+cc] + g2*sR[j][2*3+cc];
                sG[j][r*4+3] = g0*rel0 + g1*rel1 + g2*rel2 + sG[p][r*4+3];
            }
        }
        g_root[b*3+0] = sG[0][3];
        g_root[b*3+1] = sG[0][7];
        g_root[b*3+2] = sG[0][11];
    }
    __syncthreads();

    if (t < NJ) {
        float j0 = sJ[t][0], j1 = sJ[t][1], j2 = sJ[t][2];
#pragma unroll
        for (int r = 0; r < 3; r++) {
            float g0 = sG[t][r*4+0], g1 = sG[t][r*4+1], g2 = sG[t][r*4+2], gt = sG[t][r*4+3];
            float* A = &g_A[((size_t)b*NJ + t)*12 + r*4];
            A[0] = g0; A[1] = g1; A[2] = g2;
            A[3] = gt - (g0*j0 + g1*j1 + g2*j2);
            out[OFF_J + (size_t)b*72 + t*3 + r] = gt - sG[0][r*4+3];
        }
    }
}

// ============================================================================
// Kernel 4: pack GEMM A fragments + skin A-mat fragments (hi/lo) (R12)
// ============================================================================
#define PACKA_THREADS (MBLK * KA * 8 * 32)
#define PACKAM_THREADS (BTB * 3 * 12 * 32)
__global__ void __launch_bounds__(256) k_pack() {
    int gidx = blockIdx.x * 256 + threadIdx.x;
    if (gidx < PACKA_THREADS) {
        int idx = gidx;
        int t = idx & 31;
        int m_sub = (idx >> 5) & 7;
        int rest = idx >> 8;
        int ka = rest % KA;
        int m_blk = rest / KA;
        int g = t >> 2, tig = t & 3;
        int row0 = m_blk * 128 + m_sub * 16 + g;
        int k0 = ka * 8 + tig;
        uint4 a;
        a.x = tf32_bits(g_AB[row0 * KP + k0]);
        a.y = tf32_bits(g_AB[(row0 + 8) * KP + k0]);
        a.z = tf32_bits(g_AB[row0 * KP + k0 + 4]);
        a.w = tf32_bits(g_AB[(row0 + 8) * KP + k0 + 4]);
        ((uint4*)g_Afrag)[((size_t)(m_blk * KA + ka) * 8 + m_sub) * 32 + t] = a;
    } else {
        int idx = gidx - PACKA_THREADS;
        int lane = idx & 31;
        int atom = idx >> 5;
        int na = atom % 12;
        int rest = atom / 12;
        int ka = rest % 3;
        int bt = rest / 3;
        int g = lane >> 2, tig = lane & 3;
        int b = bt * 8 + g;
        int j0 = ka * 8 + tig;
        float a0 = g_A[((size_t)b * NJ + j0) * 12 + na];
        float a1 = g_A[((size_t)b * NJ + j0 + 4) * 12 + na];
        uint2 hi, lo;
        split_tf32(a0, hi.x, lo.x);
        split_tf32(a1, hi.y, lo.y);
        g_Afh[idx] = hi;
        g_Afl[idx] = lo;
    }
}

// ============================================================================
// Kernel 5: tf32 tensor-core GEMM (R12, 2 k-atoms/stage) — bf16 epilogue
// ============================================================================
__global__ void __launch_bounds__(256, 2) k_gemm() {
    __shared__ uint4 sA[2][2][8][32];
    __shared__ uint2 sB[2][2][16][32];
    int n_blk = blockIdx.x;
    int m_blk = blockIdx.y;
    int tid = threadIdx.x;
    int lane = tid & 31;
    int wid = tid >> 5;
    int wm = wid >> 1;
    int wn = wid & 1;

    const uint4* gA = (const uint4*)g_Afrag + (size_t)m_blk * KA * 256;
    const uint2* gB = (const uint2*)g_Bfrag + (size_t)n_blk * KA * 512;

    float4 acc[2][8];
#pragma unroll
    for (int i = 0; i < 2; i++)
#pragma unroll
        for (int j = 0; j < 8; j++) acc[i][j] = make_float4(0.f, 0.f, 0.f, 0.f);

    uint4 pa[2];
    uint2 pb0[2], pb1[2];
#pragma unroll
    for (int u = 0; u < 2; u++) {
        pa[u]  = gA[u * 256 + tid];
        pb0[u] = gB[u * 512 + tid];
        pb1[u] = gB[u * 512 + tid + 256];
    }

    int a_ms = tid >> 5;
    int b_ns0 = tid >> 5;
    int b_ns1 = 8 + (tid >> 5);

#pragma unroll
    for (int s = 0; s < KA / 2; s++) {
        int buf = s & 1;
#pragma unroll
        for (int u = 0; u < 2; u++) {
            sA[buf][u][a_ms][lane] = pa[u];
            sB[buf][u][b_ns0][lane] = pb0[u];
            sB[buf][u][b_ns1][lane] = pb1[u];
        }
        __syncthreads();
        if (s + 1 < KA / 2) {
#pragma unroll
            for (int u = 0; u < 2; u++) {
                int ka = 2 * (s + 1) + u;
                pa[u]  = gA[ka * 256 + tid];
                pb0[u] = gB[ka * 512 + tid];
                pb1[u] = gB[ka * 512 + tid + 256];
            }
        }
#pragma unroll
        for (int u = 0; u < 2; u++) {
            uint4 af[2];
            af[0] = sA[buf][u][wm * 2 + 0][lane];
            af[1] = sA[buf][u][wm * 2 + 1][lane];
            uint2 bf[8];
#pragma unroll
            for (int j = 0; j < 8; j++) bf[j] = sB[buf][u][wn * 8 + j][lane];
#pragma unroll
            for (int i = 0; i < 2; i++)
#pragma unroll
                for (int j = 0; j < 8; j++)
                    mma_tf32(acc[i][j], af[i], bf[j]);
        }
    }

    int g = lane >> 2, tig = lane & 3;
#pragma unroll
    for (int i = 0; i < 2; i++) {
        int r0 = m_blk * 128 + (wm * 2 + i) * 16 + g;
#pragma unroll
        for (int j = 0; j < 8; j++) {
            int c = n_blk * 128 + (wn * 8 + j) * 8 + tig * 2;
            *(uint32_t*)&g_vposed[(size_t)r0 * NPAD + c]       = bf16x2_pack(acc[i][j].x, acc[i][j].y);
            *(uint32_t*)&g_vposed[(size_t)(r0 + 8) * NPAD + c] = bf16x2_pack(acc[i][j].z, acc[i][j].w);
        }
    }
}

// ============================================================================
// Kernel 6: tensor-core skinning (R12 structure) — bf16 vposed reads
// ============================================================================
__global__ void __launch_bounds__(256, 3) k_skin_tc(const float* __restrict__ vtmpl,
                                                    float* __restrict__ out_verts) {
    __shared__ uint2 sAh[3 * 12 * 32];
    __shared__ uint2 sAl[3 * 12 * 32];
    __shared__ float sP[8][385];
    __shared__ float sRoot[8][3];
    int vb = blockIdx.x;
    int bt = blockIdx.y;
    int v0 = vb * 128;
    int b0 = bt * 8;
    int tid = threadIdx.x;

    {
        const uint2* gh = g_Afh + (size_t)bt * 1152;
        const uint2* gl = g_Afl + (size_t)bt * 1152;
#pragma unroll
        for (int r = 0; r < 5; r++) {
            int i = tid + r * 256;
            if (i < 1152) { sAh[i] = gh[i]; sAl[i] = gl[i]; }
        }
    }
#pragma unroll
    for (int k = 0; k < 12; k++) {
        int idx = tid + k * 256;
        int bi = idx / 384;
        int off = idx % 384;
        int gcol = v0 * 3 + off;
        float tpl = (gcol < NCOL) ? vtmpl[gcol] : 0.f;
        sP[bi][off] = __bfloat162float(g_vposed[(size_t)(b0 + bi) * NPAD + gcol]) + tpl;
    }
    if (tid < 24) sRoot[tid / 3][tid % 3] = g_root[(b0 + tid / 3) * 3 + tid % 3];
    __syncthreads();

    int lane = tid & 31;
    int ma = tid >> 5;
    int g = lane >> 2, tig = lane & 3;

    float4 acc[12];
#pragma unroll
    for (int i = 0; i < 12; i++) acc[i] = make_float4(0.f, 0.f, 0.f, 0.f);

#pragma unroll
    for (int ka = 0; ka < 3; ka++) {
        uint4 wh = g_Wfh[(((size_t)vb * 3 + ka) * 8 + ma) * 32 + lane];
#pragma unroll
        for (int na = 0; na < 12; na++) {
            uint2 bh = sAh[(ka * 12 + na) * 32 + lane];
            uint2 bl = sAl[(ka * 12 + na) * 32 + lane];
            mma_tf32(acc[na], wh, bh);
            mma_tf32(acc[na], wh, bl);
        }
    }

    int vl0 = ma * 16 + g;
#pragma unroll
    for (int pp = 0; pp < 4; pp++) {
        int vl = vl0 + (pp >> 1) * 8;
        int bi = 2 * tig + (pp & 1);
        int v = v0 + vl;
        if (v < NV) {
            float T[12];
#pragma unroll
            for (int na = 0; na < 12; na++) {
                float4 a = acc[na];
                T[na] = (pp == 0) ? a.x : (pp == 1) ? a.y : (pp == 2) ? a.z : a.w;
            }
            float px = sP[bi][vl * 3 + 0];
            float py = sP[bi][vl * 3 + 1];
            float pz = sP[bi][vl * 3 + 2];
            float ox = T[0]*px + T[1]*py + T[2] *pz + T[3]  - sRoot[bi][0];
            float oy = T[4]*px + T[5]*py + T[6] *pz + T[7]  - sRoot[bi][1];
            float oz = T[8]*px + T[9]*py + T[10]*pz + T[11] - sRoot[bi][2];
            size_t o = (size_t)(b0 + bi) * NCOL + (size_t)v * 3;
            out_verts[o + 0] = ox;
            out_verts[o + 1] = oy;
            out_verts[o + 2] = oz;
        }
    }
}

// ============================================================================
// Kernel 7: jfv (R12) — 2 batches / block, f32x2 packed.
// ============================================================================
__global__ void __launch_bounds__(256) k_jfv(const float* __restrict__ verts,
                                             const float* __restrict__ Jh,
                                             float* __restrict__ out_jfv) {
    int b0 = blockIdx.x * 2;
    int tid = threadIdx.x;
    u64 acc2[51];
#pragma unroll
    for (int i = 0; i < 51; i++) acc2[i] = 0ull;

    const float* va_base = verts + (size_t)b0 * NCOL;
    const float* vb_base = va_base + NCOL;
    for (int v = tid; v < NV; v += 256) {
        const float* va = va_base + (size_t)v * 3;
        const float* vb = vb_base + (size_t)v * 3;
        u64 x2 = pack2(va[0], vb[0]);
        u64 y2 = pack2(va[1], vb[1]);
        u64 z2 = pack2(va[2], vb[2]);
#pragma unroll
        for (int j = 0; j < 17; j++) {
            float jr = Jh[j * NV + v];
            u64 jr2 = pack2(jr, jr);
            acc2[j*3+0] = ffma2(jr2, x2, acc2[j*3+0]);
            acc2[j*3+1] = ffma2(jr2, y2, acc2[j*3+1]);
            acc2[j*3+2] = ffma2(jr2, z2, acc2[j*3+2]);
        }
    }

    float a[102];
#pragma unroll
    for (int i = 0; i < 51; i++) {
        float2 f = unpack2(acc2[i]);
        a[i] = f.x;
        a[51 + i] = f.y;
    }

    __shared__ float red[8][102];
    int lane = tid & 31, warp = tid >> 5;
#pragma unroll
    for (int i = 0; i < 102; i++) {
        float x = a[i];
        for (int off = 16; off; off >>= 1) x += __shfl_down_sync(0xffffffffu, x, off);
        if (lane == 0) red[warp][i] = x;
    }
    __syncthreads();
    if (tid < 102) {
        float s = 0.f;
#pragma unroll
        for (int w = 0; w < 8; w++) s += red[w][tid];
        red[0][tid] = s;
    }
    __syncthreads();
    if (tid < 102) {
        int bb = tid / 51;
        int jk = tid % 51;
        int k = jk % 3;
        float val = red[0][tid] - red[0][bb * 51 + k];
        out_jfv[(size_t)(b0 + bb) * 51 + jk] = val;
    }
}

// ============================================================================
extern "C" void kernel_launch(void* const* d_in, const int* in_sizes, int n_in,
                              void* d_out, int out_size) {
    const float* pose      = (const float*)d_in[0];
    const float* betas     = (const float*)d_in[1];
    const float* gorient   = (const float*)d_in[2];
    const float* vtmpl     = (const float*)d_in[3];
    const float* shapedirs = (const float*)d_in[4];
    const float* posedirs  = (const float*)d_in[5];
    const float* Jreg      = (const float*)d_in[6];
    const float* Jh        = (const float*)d_in[7];
    const float* wgt       = (const float*)d_in[8];
    float* out = (float*)d_out;

    k_jreg_part<<<NJ * JCH, 256>>>(Jreg, vtmpl, shapedirs);
    k_front<<<BFRAG_BLOCKS + (NVB * 3 * 8 * 32) / 256, 256>>>(shapedirs, posedirs, wgt);
    k_jred<<<1, 256>>>();
    k_batch<<<BATCH, 32>>>(pose, betas, gorient, out);
    k_pack<<<(PACKA_THREADS + PACKAM_THREADS) / 256, 256>>>();
    k_gemm<<<dim3(NBLK, MBLK), 256>>>();
    k_skin_tc<<<dim3(NVB, BTB), 256>>>(vtmpl, out + OFF_VERTS);
    k_jfv<<<BATCH / 2, 256>>>(out + OFF_VERTS, Jh, out + OFF_F);
}

// round 15
// speedup vs baseline: 1.5470x; 1.1837x over previous
#include <cuda_runtime.h>
#include <cuda_bf16.h>
#include <cuda_fp16.h>
#include <math.h>
#include <stdint.h>

#define BATCH 1024
#define NV    6890
#define NJ    24
#define NB    10
#define NP    207
#define KP    224          // 10 betas + 207 pose_feature + 7 pad
#define KA    28           // KP / 8 k-atoms
#define NCOL  20670        // V*3
#define NPAD  20736        // padded N (162 * 128)
#define NBLK  162          // NPAD / 128
#define MBLK  8            // BATCH / 128
#define NVB   54           // vert tiles of 128 (54*128 = 6912)
#define BTB   128          // batch tiles of 8
#define JCH   8            // jreg v-chunks per joint
#define CHSZ  862          // ceil(NV/JCH)

// ---------------- scratch (device globals) ----------------
__device__ float g_Bfrag[NBLK * KA * 16 * 32 * 2];   // tf32 B fragments (18.6 MB)
__device__ float g_Afrag[MBLK * KA * 8 * 32 * 4];    // tf32 A fragments (917 KB)
__device__ __nv_bfloat16 g_vposed[BATCH * NPAD];     // v_posed minus template (42.5 MB, bf16)
__device__ float g_AB[BATCH * KP];                   // per-batch GEMM A rows
__device__ float g_A[BATCH * NJ * 12];               // per-batch skinning transforms (3x4)
__device__ float g_root[BATCH * 3];                  // root joint
__device__ float g_Jt[NJ * 3];
__device__ float g_Jsd[NJ * 3 * NB];
__device__ float g_Jpart[NJ * JCH * 33];             // jreg partials
__device__ __half g_Jh16[17 * NV];                   // fp16 copy of J_regressor_h36m
// skinning tensor-core fragments (W: single tf32; A: hi/lo split)
__device__ uint4 g_Wfh[NVB * 3 * 8 * 32];
__device__ uint2 g_Afh[BTB * 3 * 12 * 32];
__device__ uint2 g_Afl[BTB * 3 * 12 * 32];

__constant__ int c_parents[NJ] = {-1,0,0,0,1,2,3,4,5,6,7,8,9,9,9,12,13,14,16,17,18,19,20,21};

#define OFF_VERTS 0
#define OFF_J     (BATCH * NCOL)
#define OFF_R     (OFF_J + BATCH * NJ * 3)
#define OFF_F     (OFF_R + BATCH * NJ * 9)

// ---------------- helpers ----------------
__device__ __forceinline__ uint32_t tf32_bits(float x) {
    uint32_t u;
    asm("cvt.rna.tf32.f32 %0, %1;" : "=r"(u) : "f"(x));
    return u;
}
__device__ __forceinline__ void mma_tf32(float4& d, uint4 a, uint2 b) {
    asm volatile(
        "mma.sync.aligned.m16n8k8.row.col.f32.tf32.tf32.f32 "
        "{%0,%1,%2,%3}, {%4,%5,%6,%7}, {%8,%9}, {%0,%1,%2,%3};"
        : "+f"(d.x), "+f"(d.y), "+f"(d.z), "+f"(d.w)
        : "r"(a.x), "r"(a.y), "r"(a.z), "r"(a.w), "r"(b.x), "r"(b.y));
}
// pack (lo, hi) floats into bf16x2 word: low 16 bits = lo
__device__ __forceinline__ uint32_t bf16x2_pack(float lo, float hi) {
    uint32_t d;
    asm("cvt.rn.bf16x2.f32 %0, %1, %2;" : "=r"(d) : "f"(hi), "f"(lo));
    return d;
}
__device__ __forceinline__ void prefetch_l1(const void* p) {
    asm volatile("prefetch.global.L1 [%0];" :: "l"(p));
}
typedef unsigned long long u64;
__device__ __forceinline__ u64 pack2(float x, float y) {
    u64 r; asm("mov.b64 %0, {%1, %2};" : "=l"(r) : "f"(x), "f"(y)); return r;
}
__device__ __forceinline__ u64 ffma2(u64 a, u64 b, u64 c) {
    u64 d; asm("fma.rn.f32x2 %0, %1, %2, %3;" : "=l"(d) : "l"(a), "l"(b), "l"(c)); return d;
}
__device__ __forceinline__ float2 unpack2(u64 v) {
    float2 f; asm("mov.b64 {%0, %1}, %2;" : "=f"(f.x), "=f"(f.y) : "l"(v)); return f;
}
__device__ __forceinline__ void split_tf32(float x, uint32_t& hi, uint32_t& lo) {
    hi = tf32_bits(x);
    lo = tf32_bits(x - __uint_as_float(hi));
}

// ============================================================================
// Kernel 1a: jreg partials — 8 v-chunks per joint, 192 blocks (R13)
// ============================================================================
__global__ void __launch_bounds__(256) k_jreg_part(const float* __restrict__ Jreg,
                                                   const float* __restrict__ vtmpl,
                                                   const float* __restrict__ shapedirs) {
    int j = blockIdx.x >> 3;
    int c = blockIdx.x & 7;
    int tid = threadIdx.x;
    int vbeg = c * CHSZ;
    int vend = vbeg + CHSZ; if (vend > NV) vend = NV;
    float acc[33];
#pragma unroll
    for (int i = 0; i < 33; i++) acc[i] = 0.f;
    for (int v = vbeg + tid; v < vend; v += 256) {
        float r = Jreg[j * NV + v];
#pragma unroll
        for (int k = 0; k < 3; k++) {
            acc[k] = fmaf(r, vtmpl[v * 3 + k], acc[k]);
#pragma unroll
            for (int l = 0; l < NB; l++)
                acc[3 + k * NB + l] = fmaf(r, shapedirs[(v * 3 + k) * NB + l], acc[3 + k * NB + l]);
        }
    }
    __shared__ float part[8][33];
    int lane = tid & 31, warp = tid >> 5;
#pragma unroll
    for (int i = 0; i < 33; i++) {
        float x = acc[i];
        for (int off = 16; off; off >>= 1) x += __shfl_down_sync(0xffffffffu, x, off);
        if (lane == 0) part[warp][i] = x;
    }
    __syncthreads();
    if (tid < 33) {
        float s = 0.f;
#pragma unroll
        for (int w = 0; w < 8; w++) s += part[w][tid];
        g_Jpart[blockIdx.x * 33 + tid] = s;
    }
}

// ============================================================================
// Kernel 1b: tiny jreg reduce (1 block)
// ============================================================================
__global__ void k_jred() {
    int tid = threadIdx.x;
    for (int i = tid; i < NJ * 33; i += 256) {
        int j = i / 33, e = i % 33;
        float s = 0.f;
#pragma unroll
        for (int c = 0; c < JCH; c++) s += g_Jpart[(j * JCH + c) * 33 + e];
        if (e < 3) g_Jt[j * 3 + e] = s;
        else       g_Jsd[j * 30 + (e - 3)] = s;
    }
}

// ============================================================================
// Kernel 1c: convert J_regressor_h36m to fp16 (halves jfv's Jh L2 traffic;
// fp16 not bf16: measured bf16 error on output 3 was 2.68e-3, fp16 is 8x finer)
// ============================================================================
__global__ void __launch_bounds__(256) k_jh16(const float* __restrict__ Jh) {
    int idx = blockIdx.x * 256 + threadIdx.x;
    if (idx < 17 * NV) g_Jh16[idx] = __float2half_rn(Jh[idx]);
}

// ============================================================================
// Kernel 2: build B fragments for GEMM + W fragments (single tf32) (R13)
// ============================================================================
#define BFRAG_BLOCKS (NBLK * KA)
__global__ void __launch_bounds__(256) k_front(const float* __restrict__ shapedirs,
                                               const float* __restrict__ posedirs,
                                               const float* __restrict__ wgt) {
    int tid = threadIdx.x;
    if (blockIdx.x < BFRAG_BLOCKS) {
        __shared__ float sW8[8][128];
        int n_blk = blockIdx.x % NBLK;
        int ka = blockIdx.x / NBLK;
#pragma unroll
        for (int r = 0; r < 4; r++) {
            int e = tid + r * 256;
            int kk = e >> 7;
            int nn = e & 127;
            int k = ka * 8 + kk;
            int n = n_blk * 128 + nn;
            float val = 0.f;
            if (n < NCOL) {
                if (k < NB)            val = shapedirs[n * NB + k];
                else if (k < NB + NP)  val = posedirs[(k - NB) * NCOL + n];
            }
            sW8[kk][nn] = val;
        }
        __syncthreads();
        float2* gB = (float2*)g_Bfrag;
#pragma unroll
        for (int r = 0; r < 2; r++) {
            int e = tid + r * 256;
            int n_sub = e >> 5;
            int t = e & 31;
            int g = t >> 2, tig = t & 3;
            float b0 = sW8[tig][n_sub * 8 + g];
            float b1 = sW8[tig + 4][n_sub * 8 + g];
            float2 v;
            v.x = __uint_as_float(tf32_bits(b0));
            v.y = __uint_as_float(tf32_bits(b1));
            gB[((size_t)(n_blk * KA + ka) * 16 + n_sub) * 32 + t] = v;
        }
    } else {
        // W skin fragments (single tf32)
        int idx = (blockIdx.x - BFRAG_BLOCKS) * 256 + tid;
        int lane = idx & 31;
        int atom = idx >> 5;
        int ma = atom & 7;
        int rest = atom >> 3;
        int ka = rest % 3;
        int vb = rest / 3;
        int g = lane >> 2, tig = lane & 3;
        int v0 = vb * 128 + ma * 16 + g;
        int j0 = ka * 8 + tig;
        float w00 = (v0     < NV) ? wgt[v0 * NJ + j0]           : 0.f;
        float w01 = (v0     < NV) ? wgt[v0 * NJ + j0 + 4]       : 0.f;
        float w10 = (v0 + 8 < NV) ? wgt[(v0 + 8) * NJ + j0]     : 0.f;
        float w11 = (v0 + 8 < NV) ? wgt[(v0 + 8) * NJ + j0 + 4] : 0.f;
        uint4 hi;
        hi.x = tf32_bits(w00);
        hi.y = tf32_bits(w10);
        hi.z = tf32_bits(w01);
        hi.w = tf32_bits(w11);
        g_Wfh[idx] = hi;
    }
}

// ============================================================================
// Kernel 3: per-batch rodrigues / chain / A matrices / outputs J & R (R13)
// ============================================================================
__global__ void k_batch(const float* __restrict__ pose,
                        const float* __restrict__ betas,
                        const float* __restrict__ gorient,
                        float* __restrict__ out) {
    int b = blockIdx.x;
    int t = threadIdx.x;
    __shared__ float sR[NJ][9];
    __shared__ float sJ[NJ][3];
    __shared__ float sG[NJ][12];

    if (t < NJ) {
        float rx, ry, rz;
        if (t == 0) { rx = gorient[b*3+0]; ry = gorient[b*3+1]; rz = gorient[b*3+2]; }
        else { const float* p = pose + b*69 + (t-1)*3; rx = p[0]; ry = p[1]; rz = p[2]; }
        float xa = rx + 1e-8f, ya = ry + 1e-8f, za = rz + 1e-8f;
        float angle = sqrtf(xa*xa + ya*ya + za*za);
        float inv = 1.f / angle;
        float ax = rx*inv, ay = ry*inv, az = rz*inv;
        float s = sinf(angle), c = cosf(angle);
        float K[9] = {0.f,-az,ay, az,0.f,-ax, -ay,ax,0.f};
        float R[9];
#pragma unroll
        for (int r = 0; r < 3; r++)
#pragma unroll
            for (int cc = 0; cc < 3; cc++) {
                float k2 = 0.f;
#pragma unroll
                for (int m = 0; m < 3; m++) k2 += K[r*3+m] * K[m*3+cc];
                R[r*3+cc] = (r==cc ? 1.f : 0.f) + s*K[r*3+cc] + (1.f - c)*k2;
            }
#pragma unroll
        for (int i = 0; i < 9; i++) sR[t][i] = R[i];
#pragma unroll
        for (int i = 0; i < 9; i++) out[OFF_R + (size_t)b*216 + t*9 + i] = R[i];
        if (t >= 1) {
#pragma unroll
            for (int i = 0; i < 9; i++) {
                float id = (i==0 || i==4 || i==8) ? 1.f : 0.f;
                g_AB[b*KP + NB + (t-1)*9 + i] = R[i] - id;
            }
        }
#pragma unroll
        for (int k = 0; k < 3; k++) {
            float jr = g_Jt[t*3 + k];
#pragma unroll
            for (int l = 0; l < NB; l++)
                jr = fmaf(betas[b*NB + l], g_Jsd[t*30 + k*NB + l], jr);
            sJ[t][k] = jr;
        }
    }
    if (t < NB) g_AB[b*KP + t] = betas[b*NB + t];
    if (t == 24) {
#pragma unroll
        for (int i = NB + NP; i < KP; i++) g_AB[b*KP + i] = 0.f;
    }
    __syncthreads();

    if (t == 0) {
#pragma unroll
        for (int r = 0; r < 3; r++) {
            sG[0][r*4+0] = sR[0][r*3+0];
            sG[0][r*4+1] = sR[0][r*3+1];
            sG[0][r*4+2] = sR[0][r*3+2];
            sG[0][r*4+3] = sJ[0][r];
        }
        for (int j = 1; j < NJ; j++) {
            int p = c_parents[j];
            float rel0 = sJ[j][0] - sJ[p][0];
            float rel1 = sJ[j][1] - sJ[p][1];
            float rel2 = sJ[j][2] - sJ[p][2];
#pragma unroll
            for (int r = 0; r < 3; r++) {
                float g0 = sG[p][r*4+0], g1 = sG[p][r*4+1], g2 = sG[p][r*4+2];
#pragma unroll
                for (int cc = 0; cc < 3; cc++)
                    sG[j][r*4+cc] = g0*sR[j][0*3+cc] + g1*sR[j][1*3+cc] + g2*sR[j][2*3+cc];
                sG[j][r*4+3] = g0*rel0 + g1*rel1 + g2*rel2 + sG[p][r*4+3];
            }
        }
        g_root[b*3+0] = sG[0][3];
        g_root[b*3+1] = sG[0][7];
        g_root[b*3+2] = sG[0][11];
    }
    __syncthreads();

    if (t < NJ) {
        float j0 = sJ[t][0], j1 = sJ[t][1], j2 = sJ[t][2];
#pragma unroll
        for (int r = 0; r < 3; r++) {
            float g0 = sG[t][r*4+0], g1 = sG[t][r*4+1], g2 = sG[t][r*4+2], gt = sG[t][r*4+3];
            float* A = &g_A[((size_t)b*NJ + t)*12 + r*4];
            A[0] = g0; A[1] = g1; A[2] = g2;
            A[3] = gt - (g0*j0 + g1*j1 + g2*j2);
            out[OFF_J + (size_t)b*72 + t*3 + r] = gt - sG[0][r*4+3];
        }
    }
}

// ============================================================================
// Kernel 4: pack GEMM A fragments + skin A-mat fragments (hi/lo) (R13)
// ============================================================================
#define PACKA_THREADS (MBLK * KA * 8 * 32)
#define PACKAM_THREADS (BTB * 3 * 12 * 32)
__global__ void __launch_bounds__(256) k_pack() {
    int gidx = blockIdx.x * 256 + threadIdx.x;
    if (gidx < PACKA_THREADS) {
        int idx = gidx;
        int t = idx & 31;
        int m_sub = (idx >> 5) & 7;
        int rest = idx >> 8;
        int ka = rest % KA;
        int m_blk = rest / KA;
        int g = t >> 2, tig = t & 3;
        int row0 = m_blk * 128 + m_sub * 16 + g;
        int k0 = ka * 8 + tig;
        uint4 a;
        a.x = tf32_bits(g_AB[row0 * KP + k0]);
        a.y = tf32_bits(g_AB[(row0 + 8) * KP + k0]);
        a.z = tf32_bits(g_AB[row0 * KP + k0 + 4]);
        a.w = tf32_bits(g_AB[(row0 + 8) * KP + k0 + 4]);
        ((uint4*)g_Afrag)[((size_t)(m_blk * KA + ka) * 8 + m_sub) * 32 + t] = a;
    } else {
        int idx = gidx - PACKA_THREADS;
        int lane = idx & 31;
        int atom = idx >> 5;
        int na = atom % 12;
        int rest = atom / 12;
        int ka = rest % 3;
        int bt = rest / 3;
        int g = lane >> 2, tig = lane & 3;
        int b = bt * 8 + g;
        int j0 = ka * 8 + tig;
        float a0 = g_A[((size_t)b * NJ + j0) * 12 + na];
        float a1 = g_A[((size_t)b * NJ + j0 + 4) * 12 + na];
        uint2 hi, lo;
        split_tf32(a0, hi.x, lo.x);
        split_tf32(a1, hi.y, lo.y);
        g_Afh[idx] = hi;
        g_Afl[idx] = lo;
    }
}

// ============================================================================
// Kernel 5: tf32 tensor-core GEMM (R13, 2 k-atoms/stage, bf16 epilogue)
// ============================================================================
__global__ void __launch_bounds__(256, 2) k_gemm() {
    __shared__ uint4 sA[2][2][8][32];
    __shared__ uint2 sB[2][2][16][32];
    int n_blk = blockIdx.x;
    int m_blk = blockIdx.y;
    int tid = threadIdx.x;
    int lane = tid & 31;
    int wid = tid >> 5;
    int wm = wid >> 1;
    int wn = wid & 1;

    const uint4* gA = (const uint4*)g_Afrag + (size_t)m_blk * KA * 256;
    const uint2* gB = (const uint2*)g_Bfrag + (size_t)n_blk * KA * 512;

    float4 acc[2][8];
#pragma unroll
    for (int i = 0; i < 2; i++)
#pragma unroll
        for (int j = 0; j < 8; j++) acc[i][j] = make_float4(0.f, 0.f, 0.f, 0.f);

    uint4 pa[2];
    uint2 pb0[2], pb1[2];
#pragma unroll
    for (int u = 0; u < 2; u++) {
        pa[u]  = gA[u * 256 + tid];
        pb0[u] = gB[u * 512 + tid];
        pb1[u] = gB[u * 512 + tid + 256];
    }

    int a_ms = tid >> 5;
    int b_ns0 = tid >> 5;
    int b_ns1 = 8 + (tid >> 5);

#pragma unroll
    for (int s = 0; s < KA / 2; s++) {
        int buf = s & 1;
#pragma unroll
        for (int u = 0; u < 2; u++) {
            sA[buf][u][a_ms][lane] = pa[u];
            sB[buf][u][b_ns0][lane] = pb0[u];
            sB[buf][u][b_ns1][lane] = pb1[u];
        }
        __syncthreads();
        if (s + 1 < KA / 2) {
#pragma unroll
            for (int u = 0; u < 2; u++) {
                int ka = 2 * (s + 1) + u;
                pa[u]  = gA[ka * 256 + tid];
                pb0[u] = gB[ka * 512 + tid];
                pb1[u] = gB[ka * 512 + tid + 256];
            }
        }
#pragma unroll
        for (int u = 0; u < 2; u++) {
            uint4 af[2];
            af[0] = sA[buf][u][wm * 2 + 0][lane];
            af[1] = sA[buf][u][wm * 2 + 1][lane];
            uint2 bf[8];
#pragma unroll
            for (int j = 0; j < 8; j++) bf[j] = sB[buf][u][wn * 8 + j][lane];
#pragma unroll
            for (int i = 0; i < 2; i++)
#pragma unroll
                for (int j = 0; j < 8; j++)
                    mma_tf32(acc[i][j], af[i], bf[j]);
        }
    }

    int g = lane >> 2, tig = lane & 3;
#pragma unroll
    for (int i = 0; i < 2; i++) {
        int r0 = m_blk * 128 + (wm * 2 + i) * 16 + g;
#pragma unroll
        for (int j = 0; j < 8; j++) {
            int c = n_blk * 128 + (wn * 8 + j) * 8 + tig * 2;
            *(uint32_t*)&g_vposed[(size_t)r0 * NPAD + c]       = bf16x2_pack(acc[i][j].x, acc[i][j].y);
            *(uint32_t*)&g_vposed[(size_t)(r0 + 8) * NPAD + c] = bf16x2_pack(acc[i][j].z, acc[i][j].w);
        }
    }
}

// ============================================================================
// Kernel 6: tensor-core skinning (R14: W-fragment L1 prefetch kept)
// ============================================================================
__global__ void __launch_bounds__(256, 3) k_skin_tc(const float* __restrict__ vtmpl,
                                                    float* __restrict__ out_verts) {
    __shared__ uint2 sAh[3 * 12 * 32];
    __shared__ uint2 sAl[3 * 12 * 32];
    __shared__ float sP[8][385];
    __shared__ float sRoot[8][3];
    int vb = blockIdx.x;
    int bt = blockIdx.y;
    int v0 = vb * 128;
    int b0 = bt * 8;
    int tid = threadIdx.x;
    int lane = tid & 31;
    int ma = tid >> 5;

    // prefetch this warp's 3 W-fragment lines into L1 (no register pressure)
#pragma unroll
    for (int ka = 0; ka < 3; ka++)
        prefetch_l1(&g_Wfh[(((size_t)vb * 3 + ka) * 8 + ma) * 32 + lane]);

    {
        const uint2* gh = g_Afh + (size_t)bt * 1152;
        const uint2* gl = g_Afl + (size_t)bt * 1152;
#pragma unroll
        for (int r = 0; r < 5; r++) {
            int i = tid + r * 256;
            if (i < 1152) { sAh[i] = gh[i]; sAl[i] = gl[i]; }
        }
    }
#pragma unroll
    for (int k = 0; k < 12; k++) {
        int idx = tid + k * 256;
        int bi = idx / 384;
        int off = idx % 384;
        int gcol = v0 * 3 + off;
        float tpl = (gcol < NCOL) ? vtmpl[gcol] : 0.f;
        sP[bi][off] = __bfloat162float(g_vposed[(size_t)(b0 + bi) * NPAD + gcol]) + tpl;
    }
    if (tid < 24) sRoot[tid / 3][tid % 3] = g_root[(b0 + tid / 3) * 3 + tid % 3];
    __syncthreads();

    int g = lane >> 2, tig = lane & 3;

    float4 acc[12];
#pragma unroll
    for (int i = 0; i < 12; i++) acc[i] = make_float4(0.f, 0.f, 0.f, 0.f);

#pragma unroll
    for (int ka = 0; ka < 3; ka++) {
        uint4 wh = g_Wfh[(((size_t)vb * 3 + ka) * 8 + ma) * 32 + lane];
#pragma unroll
        for (int na = 0; na < 12; na++) {
            uint2 bh = sAh[(ka * 12 + na) * 32 + lane];
            uint2 bl = sAl[(ka * 12 + na) * 32 + lane];
            mma_tf32(acc[na], wh, bh);
            mma_tf32(acc[na], wh, bl);
        }
    }

    int vl0 = ma * 16 + g;
#pragma unroll
    for (int pp = 0; pp < 4; pp++) {
        int vl = vl0 + (pp >> 1) * 8;
        int bi = 2 * tig + (pp & 1);
        int v = v0 + vl;
        if (v < NV) {
            float T[12];
#pragma unroll
            for (int na = 0; na < 12; na++) {
                float4 a = acc[na];
                T[na] = (pp == 0) ? a.x : (pp == 1) ? a.y : (pp == 2) ? a.z : a.w;
            }
            float px = sP[bi][vl * 3 + 0];
            float py = sP[bi][vl * 3 + 1];
            float pz = sP[bi][vl * 3 + 2];
            float ox = T[0]*px + T[1]*py + T[2] *pz + T[3]  - sRoot[bi][0];
            float oy = T[4]*px + T[5]*py + T[6] *pz + T[7]  - sRoot[bi][1];
            float oz = T[8]*px + T[9]*py + T[10]*pz + T[11] - sRoot[bi][2];
            size_t o = (size_t)(b0 + bi) * NCOL + (size_t)v * 3;
            out_verts[o + 0] = ox;
            out_verts[o + 1] = oy;
            out_verts[o + 2] = oz;
        }
    }
}

// ============================================================================
// Kernel 7: jfv — Jh in fp16 (halved L2 traffic, 8x finer than bf16)
// ============================================================================
__global__ void __launch_bounds__(256) k_jfv(const float* __restrict__ verts,
                                             float* __restrict__ out_jfv) {
    int b0 = blockIdx.x * 2;
    int tid = threadIdx.x;
    u64 acc2[51];
#pragma unroll
    for (int i = 0; i < 51; i++) acc2[i] = 0ull;

    const float* va_base = verts + (size_t)b0 * NCOL;
    const float* vb_base = va_base + NCOL;
    for (int v = tid; v < NV; v += 256) {
        const float* va = va_base + (size_t)v * 3;
        const float* vb = vb_base + (size_t)v * 3;
        u64 x2 = pack2(va[0], vb[0]);
        u64 y2 = pack2(va[1], vb[1]);
        u64 z2 = pack2(va[2], vb[2]);
#pragma unroll
        for (int j = 0; j < 17; j++) {
            float jr = __half2float(g_Jh16[j * NV + v]);
            u64 jr2 = pack2(jr, jr);
            acc2[j*3+0] = ffma2(jr2, x2, acc2[j*3+0]);
            acc2[j*3+1] = ffma2(jr2, y2, acc2[j*3+1]);
            acc2[j*3+2] = ffma2(jr2, z2, acc2[j*3+2]);
        }
    }

    float a[102];
#pragma unroll
    for (int i = 0; i < 51; i++) {
        float2 f = unpack2(acc2[i]);
        a[i] = f.x;
        a[51 + i] = f.y;
    }

    __shared__ float red[8][102];
    int lane = tid & 31, warp = tid >> 5;
#pragma unroll
    for (int i = 0; i < 102; i++) {
        float x = a[i];
        for (int off = 16; off; off >>= 1) x += __shfl_down_sync(0xffffffffu, x, off);
        if (lane == 0) red[warp][i] = x;
    }
    __syncthreads();
    if (tid < 102) {
        float s = 0.f;
#pragma unroll
        for (int w = 0; w < 8; w++) s += red[w][tid];
        red[0][tid] = s;
    }
    __syncthreads();
    if (tid < 102) {
        int bb = tid / 51;
        int jk = tid % 51;
        int k = jk % 3;
        float val = red[0][tid] - red[0][bb * 51 + k];
        out_jfv[(size_t)(b0 + bb) * 51 + jk] = val;
    }
}

// ============================================================================
extern "C" void kernel_launch(void* const* d_in, const int* in_sizes, int n_in,
                              void* d_out, int out_size) {
    const float* pose      = (const float*)d_in[0];
    const float* betas     = (const float*)d_in[1];
    const float* gorient   = (const float*)d_in[2];
    const float* vtmpl     = (const float*)d_in[3];
    const float* shapedirs = (const float*)d_in[4];
    const float* posedirs  = (const float*)d_in[5];
    const float* Jreg      = (const float*)d_in[6];
    const float* Jh        = (const float*)d_in[7];
    const float* wgt       = (const float*)d_in[8];
    float* out = (float*)d_out;

    k_jreg_part<<<NJ * JCH, 256>>>(Jreg, vtmpl, shapedirs);
    k_jh16<<<(17 * NV + 255) / 256, 256>>>(Jh);
    k_front<<<BFRAG_BLOCKS + (NVB * 3 * 8 * 32) / 256, 256>>>(shapedirs, posedirs, wgt);
    k_jred<<<1, 256>>>();
    k_batch<<<BATCH, 32>>>(pose, betas, gorient, out);
    k_pack<<<(PACKA_THREADS + PACKAM_THREADS) / 256, 256>>>();
    k_gemm<<<dim3(NBLK, MBLK), 256>>>();
    k_skin_tc<<<dim3(NVB, BTB), 256>>>(vtmpl, out + OFF_VERTS);
    k_jfv<<<BATCH / 2, 256>>>(out + OFF_VERTS, out + OFF_F);
}

// round 16
// speedup vs baseline: 1.6675x; 1.0778x over previous
#include <cuda_runtime.h>
#include <cuda_bf16.h>
#include <cuda_fp16.h>
#include <math.h>
#include <stdint.h>

#define BATCH 1024
#define NV    6890
#define NJ    24
#define NB    10
#define NP    207
#define KP    224          // 10 betas + 207 pose_feature + 7 pad
#define KA    28           // KP / 8 k-atoms
#define NCOL  20670        // V*3
#define NPAD  20736        // padded N (162 * 128)
#define NBLK  162          // NPAD / 128
#define MBLK  8            // BATCH / 128
#define NVB   54           // vert tiles of 128 (54*128 = 6912)
#define BTB   128          // batch tiles of 8
#define JCH   8            // jreg v-chunks per joint
#define CHSZ  862          // ceil(NV/JCH)

// ---------------- scratch (device globals) ----------------
__device__ float g_Bfrag[NBLK * KA * 16 * 32 * 2];   // tf32 B fragments (18.6 MB)
__device__ float g_Afrag[MBLK * KA * 8 * 32 * 4];    // tf32 A fragments (917 KB)
__device__ __nv_bfloat16 g_vposed[BATCH * NPAD];     // v_posed minus template (42.5 MB, bf16)
__device__ float g_AB[BATCH * KP];                   // per-batch GEMM A rows
__device__ float g_A[BATCH * NJ * 12];               // per-batch skinning transforms (3x4)
__device__ float g_root[BATCH * 3];                  // root joint
__device__ float g_Jt[NJ * 3];
__device__ float g_Jsd[NJ * 3 * NB];
__device__ float g_Jpart[NJ * JCH * 33];             // jreg partials
__device__ __half g_Jh16[17 * NV];                   // fp16 copy of J_regressor_h36m
// skinning tensor-core fragments (W: single tf32; A: single tf32)
__device__ uint4 g_Wfh[NVB * 3 * 8 * 32];
__device__ uint2 g_Afh[BTB * 3 * 12 * 32];

__constant__ int c_parents[NJ] = {-1,0,0,0,1,2,3,4,5,6,7,8,9,9,9,12,13,14,16,17,18,19,20,21};

#define OFF_VERTS 0
#define OFF_J     (BATCH * NCOL)
#define OFF_R     (OFF_J + BATCH * NJ * 3)
#define OFF_F     (OFF_R + BATCH * NJ * 9)

// ---------------- helpers ----------------
__device__ __forceinline__ uint32_t tf32_bits(float x) {
    uint32_t u;
    asm("cvt.rna.tf32.f32 %0, %1;" : "=r"(u) : "f"(x));
    return u;
}
__device__ __forceinline__ void mma_tf32(float4& d, uint4 a, uint2 b) {
    asm volatile(
        "mma.sync.aligned.m16n8k8.row.col.f32.tf32.tf32.f32 "
        "{%0,%1,%2,%3}, {%4,%5,%6,%7}, {%8,%9}, {%0,%1,%2,%3};"
        : "+f"(d.x), "+f"(d.y), "+f"(d.z), "+f"(d.w)
        : "r"(a.x), "r"(a.y), "r"(a.z), "r"(a.w), "r"(b.x), "r"(b.y));
}
// pack (lo, hi) floats into bf16x2 word: low 16 bits = lo
__device__ __forceinline__ uint32_t bf16x2_pack(float lo, float hi) {
    uint32_t d;
    asm("cvt.rn.bf16x2.f32 %0, %1, %2;" : "=r"(d) : "f"(hi), "f"(lo));
    return d;
}
__device__ __forceinline__ void prefetch_l1(const void* p) {
    asm volatile("prefetch.global.L1 [%0];" :: "l"(p));
}
typedef unsigned long long u64;
__device__ __forceinline__ u64 pack2(float x, float y) {
    u64 r; asm("mov.b64 %0, {%1, %2};" : "=l"(r) : "f"(x), "f"(y)); return r;
}
__device__ __forceinline__ u64 ffma2(u64 a, u64 b, u64 c) {
    u64 d; asm("fma.rn.f32x2 %0, %1, %2, %3;" : "=l"(d) : "l"(a), "l"(b), "l"(c)); return d;
}
__device__ __forceinline__ float2 unpack2(u64 v) {
    float2 f; asm("mov.b64 {%0, %1}, %2;" : "=f"(f.x), "=f"(f.y) : "l"(v)); return f;
}

// ============================================================================
// Kernel 1a: jreg partials — 8 v-chunks per joint, 192 blocks (R15)
// ============================================================================
__global__ void __launch_bounds__(256) k_jreg_part(const float* __restrict__ Jreg,
                                                   const float* __restrict__ vtmpl,
                                                   const float* __restrict__ shapedirs) {
    int j = blockIdx.x >> 3;
    int c = blockIdx.x & 7;
    int tid = threadIdx.x;
    int vbeg = c * CHSZ;
    int vend = vbeg + CHSZ; if (vend > NV) vend = NV;
    float acc[33];
#pragma unroll
    for (int i = 0; i < 33; i++) acc[i] = 0.f;
    for (int v = vbeg + tid; v < vend; v += 256) {
        float r = Jreg[j * NV + v];
#pragma unroll
        for (int k = 0; k < 3; k++) {
            acc[k] = fmaf(r, vtmpl[v * 3 + k], acc[k]);
#pragma unroll
            for (int l = 0; l < NB; l++)
                acc[3 + k * NB + l] = fmaf(r, shapedirs[(v * 3 + k) * NB + l], acc[3 + k * NB + l]);
        }
    }
    __shared__ float part[8][33];
    int lane = tid & 31, warp = tid >> 5;
#pragma unroll
    for (int i = 0; i < 33; i++) {
        float x = acc[i];
        for (int off = 16; off; off >>= 1) x += __shfl_down_sync(0xffffffffu, x, off);
        if (lane == 0) part[warp][i] = x;
    }
    __syncthreads();
    if (tid < 33) {
        float s = 0.f;
#pragma unroll
        for (int w = 0; w < 8; w++) s += part[w][tid];
        g_Jpart[blockIdx.x * 33 + tid] = s;
    }
}

// ============================================================================
// Kernel 1b: tiny jreg reduce (1 block)
// ============================================================================
__global__ void k_jred() {
    int tid = threadIdx.x;
    for (int i = tid; i < NJ * 33; i += 256) {
        int j = i / 33, e = i % 33;
        float s = 0.f;
#pragma unroll
        for (int c = 0; c < JCH; c++) s += g_Jpart[(j * JCH + c) * 33 + e];
        if (e < 3) g_Jt[j * 3 + e] = s;
        else       g_Jsd[j * 30 + (e - 3)] = s;
    }
}

// ============================================================================
// Kernel 1c: convert J_regressor_h36m to fp16 (R15)
// ============================================================================
__global__ void __launch_bounds__(256) k_jh16(const float* __restrict__ Jh) {
    int idx = blockIdx.x * 256 + threadIdx.x;
    if (idx < 17 * NV) g_Jh16[idx] = __float2half_rn(Jh[idx]);
}

// ============================================================================
// Kernel 2: build B fragments for GEMM + W fragments (single tf32) (R15)
// ============================================================================
#define BFRAG_BLOCKS (NBLK * KA)
__global__ void __launch_bounds__(256) k_front(const float* __restrict__ shapedirs,
                                               const float* __restrict__ posedirs,
                                               const float* __restrict__ wgt) {
    int tid = threadIdx.x;
    if (blockIdx.x < BFRAG_BLOCKS) {
        __shared__ float sW8[8][128];
        int n_blk = blockIdx.x % NBLK;
        int ka = blockIdx.x / NBLK;
#pragma unroll
        for (int r = 0; r < 4; r++) {
            int e = tid + r * 256;
            int kk = e >> 7;
            int nn = e & 127;
            int k = ka * 8 + kk;
            int n = n_blk * 128 + nn;
            float val = 0.f;
            if (n < NCOL) {
                if (k < NB)            val = shapedirs[n * NB + k];
                else if (k < NB + NP)  val = posedirs[(k - NB) * NCOL + n];
            }
            sW8[kk][nn] = val;
        }
        __syncthreads();
        float2* gB = (float2*)g_Bfrag;
#pragma unroll
        for (int r = 0; r < 2; r++) {
            int e = tid + r * 256;
            int n_sub = e >> 5;
            int t = e & 31;
            int g = t >> 2, tig = t & 3;
            float b0 = sW8[tig][n_sub * 8 + g];
            float b1 = sW8[tig + 4][n_sub * 8 + g];
            float2 v;
            v.x = __uint_as_float(tf32_bits(b0));
            v.y = __uint_as_float(tf32_bits(b1));
            gB[((size_t)(n_blk * KA + ka) * 16 + n_sub) * 32 + t] = v;
        }
    } else {
        // W skin fragments (single tf32)
        int idx = (blockIdx.x - BFRAG_BLOCKS) * 256 + tid;
        int lane = idx & 31;
        int atom = idx >> 5;
        int ma = atom & 7;
        int rest = atom >> 3;
        int ka = rest % 3;
        int vb = rest / 3;
        int g = lane >> 2, tig = lane & 3;
        int v0 = vb * 128 + ma * 16 + g;
        int j0 = ka * 8 + tig;
        float w00 = (v0     < NV) ? wgt[v0 * NJ + j0]           : 0.f;
        float w01 = (v0     < NV) ? wgt[v0 * NJ + j0 + 4]       : 0.f;
        float w10 = (v0 + 8 < NV) ? wgt[(v0 + 8) * NJ + j0]     : 0.f;
        float w11 = (v0 + 8 < NV) ? wgt[(v0 + 8) * NJ + j0 + 4] : 0.f;
        uint4 hi;
        hi.x = tf32_bits(w00);
        hi.y = tf32_bits(w10);
        hi.z = tf32_bits(w01);
        hi.w = tf32_bits(w11);
        g_Wfh[idx] = hi;
    }
}

// ============================================================================
// Kernel 3: per-batch rodrigues / chain / A matrices / outputs J & R (R15)
// ============================================================================
__global__ void k_batch(const float* __restrict__ pose,
                        const float* __restrict__ betas,
                        const float* __restrict__ gorient,
                        float* __restrict__ out) {
    int b = blockIdx.x;
    int t = threadIdx.x;
    __shared__ float sR[NJ][9];
    __shared__ float sJ[NJ][3];
    __shared__ float sG[NJ][12];

    if (t < NJ) {
        float rx, ry, rz;
        if (t == 0) { rx = gorient[b*3+0]; ry = gorient[b*3+1]; rz = gorient[b*3+2]; }
        else { const float* p = pose + b*69 + (t-1)*3; rx = p[0]; ry = p[1]; rz = p[2]; }
        float xa = rx + 1e-8f, ya = ry + 1e-8f, za = rz + 1e-8f;
        float angle = sqrtf(xa*xa + ya*ya + za*za);
        float inv = 1.f / angle;
        float ax = rx*inv, ay = ry*inv, az = rz*inv;
        float s = sinf(angle), c = cosf(angle);
        float K[9] = {0.f,-az,ay, az,0.f,-ax, -ay,ax,0.f};
        float R[9];
#pragma unroll
        for (int r = 0; r < 3; r++)
#pragma unroll
            for (int cc = 0; cc < 3; cc++) {
                float k2 = 0.f;
#pragma unroll
                for (int m = 0; m < 3; m++) k2 += K[r*3+m] * K[m*3+cc];
                R[r*3+cc] = (r==cc ? 1.f : 0.f) + s*K[r*3+cc] + (1.f - c)*k2;
            }
#pragma unroll
        for (int i = 0; i < 9; i++) sR[t][i] = R[i];
#pragma unroll
        for (int i = 0; i < 9; i++) out[OFF_R + (size_t)b*216 + t*9 + i] = R[i];
        if (t >= 1) {
#pragma unroll
            for (int i = 0; i < 9; i++) {
                float id = (i==0 || i==4 || i==8) ? 1.f : 0.f;
                g_AB[b*KP + NB + (t-1)*9 + i] = R[i] - id;
            }
        }
#pragma unroll
        for (int k = 0; k < 3; k++) {
            float jr = g_Jt[t*3 + k];
#pragma unroll
            for (int l = 0; l < NB; l++)
                jr = fmaf(betas[b*NB + l], g_Jsd[t*30 + k*NB + l], jr);
            sJ[t][k] = jr;
        }
    }
    if (t < NB) g_AB[b*KP + t] = betas[b*NB + t];
    if (t == 24) {
#pragma unroll
        for (int i = NB + NP; i < KP; i++) g_AB[b*KP + i] = 0.f;
    }
    __syncthreads();

    if (t == 0) {
#pragma unroll
        for (int r = 0; r < 3; r++) {
            sG[0][r*4+0] = sR[0][r*3+0];
            sG[0][r*4+1] = sR[0][r*3+1];
            sG[0][r*4+2] = sR[0][r*3+2];
            sG[0][r*4+3] = sJ[0][r];
        }
        for (int j = 1; j < NJ; j++) {
            int p = c_parents[j];
            float rel0 = sJ[j][0] - sJ[p][0];
            float rel1 = sJ[j][1] - sJ[p][1];
            float rel2 = sJ[j][2] - sJ[p][2];
#pragma unroll
            for (int r = 0; r < 3; r++) {
                float g0 = sG[p][r*4+0], g1 = sG[p][r*4+1], g2 = sG[p][r*4+2];
#pragma unroll
                for (int cc = 0; cc < 3; cc++)
                    sG[j][r*4+cc] = g0*sR[j][0*3+cc] + g1*sR[j][1*3+cc] + g2*sR[j][2*3+cc];
                sG[j][r*4+3] = g0*rel0 + g1*rel1 + g2*rel2 + sG[p][r*4+3];
            }
        }
        g_root[b*3+0] = sG[0][3];
        g_root[b*3+1] = sG[0][7];
        g_root[b*3+2] = sG[0][11];
    }
    __syncthreads();

    if (t < NJ) {
        float j0 = sJ[t][0], j1 = sJ[t][1], j2 = sJ[t][2];
#pragma unroll
        for (int r = 0; r < 3; r++) {
            float g0 = sG[t][r*4+0], g1 = sG[t][r*4+1], g2 = sG[t][r*4+2], gt = sG[t][r*4+3];
            float* A = &g_A[((size_t)b*NJ + t)*12 + r*4];
            A[0] = g0; A[1] = g1; A[2] = g2;
            A[3] = gt - (g0*j0 + g1*j1 + g2*j2);
            out[OFF_J + (size_t)b*72 + t*3 + r] = gt - sG[0][r*4+3];
        }
    }
}

// ============================================================================
// Kernel 4: pack GEMM A fragments + skin A-mat fragments (single tf32)
// ============================================================================
#define PACKA_THREADS (MBLK * KA * 8 * 32)
#define PACKAM_THREADS (BTB * 3 * 12 * 32)
__global__ void __launch_bounds__(256) k_pack() {
    int gidx = blockIdx.x * 256 + threadIdx.x;
    if (gidx < PACKA_THREADS) {
        int idx = gidx;
        int t = idx & 31;
        int m_sub = (idx >> 5) & 7;
        int rest = idx >> 8;
        int ka = rest % KA;
        int m_blk = rest / KA;
        int g = t >> 2, tig = t & 3;
        int row0 = m_blk * 128 + m_sub * 16 + g;
        int k0 = ka * 8 + tig;
        uint4 a;
        a.x = tf32_bits(g_AB[row0 * KP + k0]);
        a.y = tf32_bits(g_AB[(row0 + 8) * KP + k0]);
        a.z = tf32_bits(g_AB[row0 * KP + k0 + 4]);
        a.w = tf32_bits(g_AB[(row0 + 8) * KP + k0 + 4]);
        ((uint4*)g_Afrag)[((size_t)(m_blk * KA + ka) * 8 + m_sub) * 32 + t] = a;
    } else {
        int idx = gidx - PACKA_THREADS;
        int lane = idx & 31;
        int atom = idx >> 5;
        int na = atom % 12;
        int rest = atom / 12;
        int ka = rest % 3;
        int bt = rest / 3;
        int g = lane >> 2, tig = lane & 3;
        int b = bt * 8 + g;
        int j0 = ka * 8 + tig;
        uint2 hi;
        hi.x = tf32_bits(g_A[((size_t)b * NJ + j0) * 12 + na]);
        hi.y = tf32_bits(g_A[((size_t)b * NJ + j0 + 4) * 12 + na]);
        g_Afh[idx] = hi;
    }
}

// ============================================================================
// Kernel 5: tf32 tensor-core GEMM (R15: 2 k-atoms/stage, bf16 epilogue)
// ============================================================================
__global__ void __launch_bounds__(256, 2) k_gemm() {
    __shared__ uint4 sA[2][2][8][32];
    __shared__ uint2 sB[2][2][16][32];
    int n_blk = blockIdx.x;
    int m_blk = blockIdx.y;
    int tid = threadIdx.x;
    int lane = tid & 31;
    int wid = tid >> 5;
    int wm = wid >> 1;
    int wn = wid & 1;

    const uint4* gA = (const uint4*)g_Afrag + (size_t)m_blk * KA * 256;
    const uint2* gB = (const uint2*)g_Bfrag + (size_t)n_blk * KA * 512;

    float4 acc[2][8];
#pragma unroll
    for (int i = 0; i < 2; i++)
#pragma unroll
        for (int j = 0; j < 8; j++) acc[i][j] = make_float4(0.f, 0.f, 0.f, 0.f);

    uint4 pa[2];
    uint2 pb0[2], pb1[2];
#pragma unroll
    for (int u = 0; u < 2; u++) {
        pa[u]  = gA[u * 256 + tid];
        pb0[u] = gB[u * 512 + tid];
        pb1[u] = gB[u * 512 + tid + 256];
    }

    int a_ms = tid >> 5;
    int b_ns0 = tid >> 5;
    int b_ns1 = 8 + (tid >> 5);

#pragma unroll
    for (int s = 0; s < KA / 2; s++) {
        int buf = s & 1;
#pragma unroll
        for (int u = 0; u < 2; u++) {
            sA[buf][u][a_ms][lane] = pa[u];
            sB[buf][u][b_ns0][lane] = pb0[u];
            sB[buf][u][b_ns1][lane] = pb1[u];
        }
        __syncthreads();
        if (s + 1 < KA / 2) {
#pragma unroll
            for (int u = 0; u < 2; u++) {
                int ka = 2 * (s + 1) + u;
                pa[u]  = gA[ka * 256 + tid];
                pb0[u] = gB[ka * 512 + tid];
                pb1[u] = gB[ka * 512 + tid + 256];
            }
        }
#pragma unroll
        for (int u = 0; u < 2; u++) {
            uint4 af[2];
            af[0] = sA[buf][u][wm * 2 + 0][lane];
            af[1] = sA[buf][u][wm * 2 + 1][lane];
            uint2 bf[8];
#pragma unroll
            for (int j = 0; j < 8; j++) bf[j] = sB[buf][u][wn * 8 + j][lane];
#pragma unroll
            for (int i = 0; i < 2; i++)
#pragma unroll
                for (int j = 0; j < 8; j++)
                    mma_tf32(acc[i][j], af[i], bf[j]);
        }
    }

    int g = lane >> 2, tig = lane & 3;
#pragma unroll
    for (int i = 0; i < 2; i++) {
        int r0 = m_blk * 128 + (wm * 2 + i) * 16 + g;
#pragma unroll
        for (int j = 0; j < 8; j++) {
            int c = n_blk * 128 + (wn * 8 + j) * 8 + tig * 2;
            *(uint32_t*)&g_vposed[(size_t)r0 * NPAD + c]       = bf16x2_pack(acc[i][j].x, acc[i][j].y);
            *(uint32_t*)&g_vposed[(size_t)(r0 + 8) * NPAD + c] = bf16x2_pack(acc[i][j].z, acc[i][j].w);
        }
    }
}

// ============================================================================
// Kernel 6: tensor-core skinning — A single tf32 (36 MMAs), 4 blocks/SM.
// ============================================================================
__global__ void __launch_bounds__(256, 4) k_skin_tc(const float* __restrict__ vtmpl,
                                                    float* __restrict__ out_verts) {
    __shared__ uint2 sAh[3 * 12 * 32];
    __shared__ float sP[8][385];
    __shared__ float sRoot[8][3];
    int vb = blockIdx.x;
    int bt = blockIdx.y;
    int v0 = vb * 128;
    int b0 = bt * 8;
    int tid = threadIdx.x;
    int lane = tid & 31;
    int ma = tid >> 5;

    // prefetch this warp's 3 W-fragment lines into L1
#pragma unroll
    for (int ka = 0; ka < 3; ka++)
        prefetch_l1(&g_Wfh[(((size_t)vb * 3 + ka) * 8 + ma) * 32 + lane]);

    {
        const uint2* gh = g_Afh + (size_t)bt * 1152;
#pragma unroll
        for (int r = 0; r < 5; r++) {
            int i = tid + r * 256;
            if (i < 1152) sAh[i] = gh[i];
        }
    }
#pragma unroll
    for (int k = 0; k < 12; k++) {
        int idx = tid + k * 256;
        int bi = idx / 384;
        int off = idx % 384;
        int gcol = v0 * 3 + off;
        float tpl = (gcol < NCOL) ? vtmpl[gcol] : 0.f;
        sP[bi][off] = __bfloat162float(g_vposed[(size_t)(b0 + bi) * NPAD + gcol]) + tpl;
    }
    if (tid < 24) sRoot[tid / 3][tid % 3] = g_root[(b0 + tid / 3) * 3 + tid % 3];
    __syncthreads();

    int g = lane >> 2, tig = lane & 3;

    float4 acc[12];
#pragma unroll
    for (int i = 0; i < 12; i++) acc[i] = make_float4(0.f, 0.f, 0.f, 0.f);

#pragma unroll
    for (int ka = 0; ka < 3; ka++) {
        uint4 wh = g_Wfh[(((size_t)vb * 3 + ka) * 8 + ma) * 32 + lane];
#pragma unroll
        for (int na = 0; na < 12; na++) {
            uint2 bh = sAh[(ka * 12 + na) * 32 + lane];
            mma_tf32(acc[na], wh, bh);
        }
    }

    int vl0 = ma * 16 + g;
#pragma unroll
    for (int pp = 0; pp < 4; pp++) {
        int vl = vl0 + (pp >> 1) * 8;
        int bi = 2 * tig + (pp & 1);
        int v = v0 + vl;
        if (v < NV) {
            float T[12];
#pragma unroll
            for (int na = 0; na < 12; na++) {
                float4 a = acc[na];
                T[na] = (pp == 0) ? a.x : (pp == 1) ? a.y : (pp == 2) ? a.z : a.w;
            }
            float px = sP[bi][vl * 3 + 0];
            float py = sP[bi][vl * 3 + 1];
            float pz = sP[bi][vl * 3 + 2];
            float ox = T[0]*px + T[1]*py + T[2] *pz + T[3]  - sRoot[bi][0];
            float oy = T[4]*px + T[5]*py + T[6] *pz + T[7]  - sRoot[bi][1];
            float oz = T[8]*px + T[9]*py + T[10]*pz + T[11] - sRoot[bi][2];
            size_t o = (size_t)(b0 + bi) * NCOL + (size_t)v * 3;
            out_verts[o + 0] = ox;
            out_verts[o + 1] = oy;
            out_verts[o + 2] = oz;
        }
    }
}

// ============================================================================
// Kernel 7: jfv — Jh in fp16 (R15)
// ============================================================================
__global__ void __launch_bounds__(256) k_jfv(const float* __restrict__ verts,
                                             float* __restrict__ out_jfv) {
    int b0 = blockIdx.x * 2;
    int tid = threadIdx.x;
    u64 acc2[51];
#pragma unroll
    for (int i = 0; i < 51; i++) acc2[i] = 0ull;

    const float* va_base = verts + (size_t)b0 * NCOL;
    const float* vb_base = va_base + NCOL;
    for (int v = tid; v < NV; v += 256) {
        const float* va = va_base + (size_t)v * 3;
        const float* vb = vb_base + (size_t)v * 3;
        u64 x2 = pack2(va[0], vb[0]);
        u64 y2 = pack2(va[1], vb[1]);
        u64 z2 = pack2(va[2], vb[2]);
#pragma unroll
        for (int j = 0; j < 17; j++) {
            float jr = __half2float(g_Jh16[j * NV + v]);
            u64 jr2 = pack2(jr, jr);
            acc2[j*3+0] = ffma2(jr2, x2, acc2[j*3+0]);
            acc2[j*3+1] = ffma2(jr2, y2, acc2[j*3+1]);
            acc2[j*3+2] = ffma2(jr2, z2, acc2[j*3+2]);
        }
    }

    float a[102];
#pragma unroll
    for (int i = 0; i < 51; i++) {
        float2 f = unpack2(acc2[i]);
        a[i] = f.x;
        a[51 + i] = f.y;
    }

    __shared__ float red[8][102];
    int lane = tid & 31, warp = tid >> 5;
#pragma unroll
    for (int i = 0; i < 102; i++) {
        float x = a[i];
        for (int off = 16; off; off >>= 1) x += __shfl_down_sync(0xffffffffu, x, off);
        if (lane == 0) red[warp][i] = x;
    }
    __syncthreads();
    if (tid < 102) {
        float s = 0.f;
#pragma unroll
        for (int w = 0; w < 8; w++) s += red[w][tid];
        red[0][tid] = s;
    }
    __syncthreads();
    if (tid < 102) {
        int bb = tid / 51;
        int jk = tid % 51;
        int k = jk % 3;
        float val = red[0][tid] - red[0][bb * 51 + k];
        out_jfv[(size_t)(b0 + bb) * 51 + jk] = val;
    }
}

// ============================================================================
extern "C" void kernel_launch(void* const* d_in, const int* in_sizes, int n_in,
                              void* d_out, int out_size) {
    const float* pose      = (const float*)d_in[0];
    const float* betas     = (const float*)d_in[1];
    const float* gorient   = (const float*)d_in[2];
    const float* vtmpl     = (const float*)d_in[3];
    const float* shapedirs = (const float*)d_in[4];
    const float* posedirs  = (const float*)d_in[5];
    const float* Jreg      = (const float*)d_in[6];
    const float* Jh        = (const float*)d_in[7];
    const float* wgt       = (const float*)d_in[8];
    float* out = (float*)d_out;

    k_jreg_part<<<NJ * JCH, 256>>>(Jreg, vtmpl, shapedirs);
    k_jh16<<<(17 * NV + 255) / 256, 256>>>(Jh);
    k_front<<<BFRAG_BLOCKS + (NVB * 3 * 8 * 32) / 256, 256>>>(shapedirs, posedirs, wgt);
    k_jred<<<1, 256>>>();
    k_batch<<<BATCH, 32>>>(pose, betas, gorient, out);
    k_pack<<<(PACKA_THREADS + PACKAM_THREADS) / 256, 256>>>();
    k_gemm<<<dim3(NBLK, MBLK), 256>>>();
    k_skin_tc<<<dim3(NVB, BTB), 256>>>(vtmpl, out + OFF_VERTS);
    k_jfv<<<BATCH / 2, 256>>>(out + OFF_VERTS, out + OFF_F);
}

// round 17
// speedup vs baseline: 1.8960x; 1.1371x over previous
#include <cuda_runtime.h>
#include <cuda_bf16.h>
#include <cuda_fp16.h>
#include <math.h>
#include <stdint.h>

#define BATCH 1024
#define NV    6890
#define NJ    24
#define NB    10
#define NP    207
#define KP    224          // 10 betas + 207 pose_feature + 7 pad
#define KA16  14           // KP / 16 k-atoms (bf16 m16n8k16)
#define NCOL  20670        // V*3
#define NPAD  20736        // padded N (162 * 128)
#define NBLK  162          // NPAD / 128
#define MBLK  8            // BATCH / 128
#define NVB   54           // vert tiles of 128
#define BTB   128          // batch tiles of 8
#define JCH   8            // jreg v-chunks per joint
#define CHSZ  862          // ceil(NV/JCH)

// ---------------- scratch (device globals) ----------------
__device__ uint2 g_Bfrag16[NBLK * KA16 * 16 * 32];  // bf16 B fragments (9.3 MB)
__device__ uint4 g_Afrag16[MBLK * KA16 * 8 * 32];   // bf16 A fragments (459 KB)
__device__ __nv_bfloat16 g_vposed[BATCH * NPAD];    // v_posed minus template (42.5 MB)
__device__ float g_AB[BATCH * KP];                  // per-batch GEMM A rows
__device__ float g_A[BATCH * NJ * 12];              // per-batch skinning transforms
__device__ float g_root[BATCH * 3];
__device__ float g_Jt[NJ * 3];
__device__ float g_Jsd[NJ * 3 * NB];
__device__ float g_Jpart[NJ * JCH * 33];
__device__ __half g_Jh16[17 * NV];                  // fp16 J_regressor_h36m
// skinning tensor-core fragments (W: single tf32; A: single tf32)
__device__ uint4 g_Wfh[NVB * 3 * 8 * 32];
__device__ uint2 g_Afh[BTB * 3 * 12 * 32];

__constant__ int c_parents[NJ] = {-1,0,0,0,1,2,3,4,5,6,7,8,9,9,9,12,13,14,16,17,18,19,20,21};

#define OFF_VERTS 0
#define OFF_J     (BATCH * NCOL)
#define OFF_R     (OFF_J + BATCH * NJ * 3)
#define OFF_F     (OFF_R + BATCH * NJ * 9)

// ---------------- helpers ----------------
__device__ __forceinline__ uint32_t tf32_bits(float x) {
    uint32_t u;
    asm("cvt.rna.tf32.f32 %0, %1;" : "=r"(u) : "f"(x));
    return u;
}
__device__ __forceinline__ void mma_tf32(float4& d, uint4 a, uint2 b) {
    asm volatile(
        "mma.sync.aligned.m16n8k8.row.col.f32.tf32.tf32.f32 "
        "{%0,%1,%2,%3}, {%4,%5,%6,%7}, {%8,%9}, {%0,%1,%2,%3};"
        : "+f"(d.x), "+f"(d.y), "+f"(d.z), "+f"(d.w)
        : "r"(a.x), "r"(a.y), "r"(a.z), "r"(a.w), "r"(b.x), "r"(b.y));
}
__device__ __forceinline__ void mma_bf16(float4& d, uint4 a, uint2 b) {
    asm volatile(
        "mma.sync.aligned.m16n8k16.row.col.f32.bf16.bf16.f32 "
        "{%0,%1,%2,%3}, {%4,%5,%6,%7}, {%8,%9}, {%0,%1,%2,%3};"
        : "+f"(d.x), "+f"(d.y), "+f"(d.z), "+f"(d.w)
        : "r"(a.x), "r"(a.y), "r"(a.z), "r"(a.w), "r"(b.x), "r"(b.y));
}
// pack (lo, hi) floats into bf16x2 word: low 16 bits = lo
__device__ __forceinline__ uint32_t bf16x2_pack(float lo, float hi) {
    uint32_t d;
    asm("cvt.rn.bf16x2.f32 %0, %1, %2;" : "=r"(d) : "f"(hi), "f"(lo));
    return d;
}
__device__ __forceinline__ void prefetch_l1(const void* p) {
    asm volatile("prefetch.global.L1 [%0];" :: "l"(p));
}
typedef unsigned long long u64;
__device__ __forceinline__ u64 pack2(float x, float y) {
    u64 r; asm("mov.b64 %0, {%1, %2};" : "=l"(r) : "f"(x), "f"(y)); return r;
}
__device__ __forceinline__ u64 ffma2(u64 a, u64 b, u64 c) {
    u64 d; asm("fma.rn.f32x2 %0, %1, %2, %3;" : "=l"(d) : "l"(a), "l"(b), "l"(c)); return d;
}
__device__ __forceinline__ float2 unpack2(u64 v) {
    float2 f; asm("mov.b64 {%0, %1}, %2;" : "=f"(f.x), "=f"(f.y) : "l"(v)); return f;
}

// ============================================================================
// Kernel 1a: jreg partials (R16)
// ============================================================================
__global__ void __launch_bounds__(256) k_jreg_part(const float* __restrict__ Jreg,
                                                   const float* __restrict__ vtmpl,
                                                   const float* __restrict__ shapedirs) {
    int j = blockIdx.x >> 3;
    int c = blockIdx.x & 7;
    int tid = threadIdx.x;
    int vbeg = c * CHSZ;
    int vend = vbeg + CHSZ; if (vend > NV) vend = NV;
    float acc[33];
#pragma unroll
    for (int i = 0; i < 33; i++) acc[i] = 0.f;
    for (int v = vbeg + tid; v < vend; v += 256) {
        float r = Jreg[j * NV + v];
#pragma unroll
        for (int k = 0; k < 3; k++) {
            acc[k] = fmaf(r, vtmpl[v * 3 + k], acc[k]);
#pragma unroll
            for (int l = 0; l < NB; l++)
                acc[3 + k * NB + l] = fmaf(r, shapedirs[(v * 3 + k) * NB + l], acc[3 + k * NB + l]);
        }
    }
    __shared__ float part[8][33];
    int lane = tid & 31, warp = tid >> 5;
#pragma unroll
    for (int i = 0; i < 33; i++) {
        float x = acc[i];
        for (int off = 16; off; off >>= 1) x += __shfl_down_sync(0xffffffffu, x, off);
        if (lane == 0) part[warp][i] = x;
    }
    __syncthreads();
    if (tid < 33) {
        float s = 0.f;
#pragma unroll
        for (int w = 0; w < 8; w++) s += part[w][tid];
        g_Jpart[blockIdx.x * 33 + tid] = s;
    }
}

// ============================================================================
// Kernel 1b: tiny jreg reduce
// ============================================================================
__global__ void k_jred() {
    int tid = threadIdx.x;
    for (int i = tid; i < NJ * 33; i += 256) {
        int j = i / 33, e = i % 33;
        float s = 0.f;
#pragma unroll
        for (int c = 0; c < JCH; c++) s += g_Jpart[(j * JCH + c) * 33 + e];
        if (e < 3) g_Jt[j * 3 + e] = s;
        else       g_Jsd[j * 30 + (e - 3)] = s;
    }
}

// ============================================================================
// Kernel 1c: convert J_regressor_h36m to fp16 (R15)
// ============================================================================
__global__ void __launch_bounds__(256) k_jh16(const float* __restrict__ Jh) {
    int idx = blockIdx.x * 256 + threadIdx.x;
    if (idx < 17 * NV) g_Jh16[idx] = __float2half_rn(Jh[idx]);
}

// ============================================================================
// Kernel 2: build bf16 B fragments (m16n8k16) + W skin fragments
// ============================================================================
#define BFRAG_BLOCKS (NBLK * KA16)
__global__ void __launch_bounds__(256) k_front(const float* __restrict__ shapedirs,
                                               const float* __restrict__ posedirs,
                                               const float* __restrict__ wgt) {
    int tid = threadIdx.x;
    if (blockIdx.x < BFRAG_BLOCKS) {
        __shared__ float sW16[16][128];
        int n_blk = blockIdx.x % NBLK;
        int ka = blockIdx.x / NBLK;         // 0..13
#pragma unroll
        for (int r = 0; r < 8; r++) {
            int e = tid + r * 256;          // 0..2047
            int kk = e >> 7;                // 0..15
            int nn = e & 127;
            int k = ka * 16 + kk;
            int n = n_blk * 128 + nn;
            float val = 0.f;
            if (n < NCOL) {
                if (k < NB)            val = shapedirs[n * NB + k];
                else if (k < NB + NP)  val = posedirs[(k - NB) * NCOL + n];
            }
            sW16[kk][nn] = val;
        }
        __syncthreads();
#pragma unroll
        for (int r = 0; r < 2; r++) {
            int e = tid + r * 256;          // 0..511
            int n_sub = e >> 5;             // 0..15
            int t = e & 31;
            int g = t >> 2, tig = t & 3;
            int n = n_sub * 8 + g;
            uint2 v;
            v.x = bf16x2_pack(sW16[2*tig    ][n], sW16[2*tig + 1][n]);
            v.y = bf16x2_pack(sW16[2*tig + 8][n], sW16[2*tig + 9][n]);
            g_Bfrag16[((size_t)(n_blk * KA16 + ka) * 16 + n_sub) * 32 + t] = v;
        }
    } else {
        // W skin fragments (single tf32)
        int idx = (blockIdx.x - BFRAG_BLOCKS) * 256 + tid;
        int lane = idx & 31;
        int atom = idx >> 5;
        int ma = atom & 7;
        int rest = atom >> 3;
        int ka = rest % 3;
        int vb = rest / 3;
        int g = lane >> 2, tig = lane & 3;
        int v0 = vb * 128 + ma * 16 + g;
        int j0 = ka * 8 + tig;
        float w00 = (v0     < NV) ? wgt[v0 * NJ + j0]           : 0.f;
        float w01 = (v0     < NV) ? wgt[v0 * NJ + j0 + 4]       : 0.f;
        float w10 = (v0 + 8 < NV) ? wgt[(v0 + 8) * NJ + j0]     : 0.f;
        float w11 = (v0 + 8 < NV) ? wgt[(v0 + 8) * NJ + j0 + 4] : 0.f;
        uint4 hi;
        hi.x = tf32_bits(w00);
        hi.y = tf32_bits(w10);
        hi.z = tf32_bits(w01);
        hi.w = tf32_bits(w11);
        g_Wfh[idx] = hi;
    }
}

// ============================================================================
// Kernel 3: per-batch rodrigues / chain / A matrices / outputs J & R (R16)
// ============================================================================
__global__ void k_batch(const float* __restrict__ pose,
                        const float* __restrict__ betas,
                        const float* __restrict__ gorient,
                        float* __restrict__ out) {
    int b = blockIdx.x;
    int t = threadIdx.x;
    __shared__ float sR[NJ][9];
    __shared__ float sJ[NJ][3];
    __shared__ float sG[NJ][12];

    if (t < NJ) {
        float rx, ry, rz;
        if (t == 0) { rx = gorient[b*3+0]; ry = gorient[b*3+1]; rz = gorient[b*3+2]; }
        else { const float* p = pose + b*69 + (t-1)*3; rx = p[0]; ry = p[1]; rz = p[2]; }
        float xa = rx + 1e-8f, ya = ry + 1e-8f, za = rz + 1e-8f;
        float angle = sqrtf(xa*xa + ya*ya + za*za);
        float inv = 1.f / angle;
        float ax = rx*inv, ay = ry*inv, az = rz*inv;
        float s = sinf(angle), c = cosf(angle);
        float K[9] = {0.f,-az,ay, az,0.f,-ax, -ay,ax,0.f};
        float R[9];
#pragma unroll
        for (int r = 0; r < 3; r++)
#pragma unroll
            for (int cc = 0; cc < 3; cc++) {
                float k2 = 0.f;
#pragma unroll
                for (int m = 0; m < 3; m++) k2 += K[r*3+m] * K[m*3+cc];
                R[r*3+cc] = (r==cc ? 1.f : 0.f) + s*K[r*3+cc] + (1.f - c)*k2;
            }
#pragma unroll
        for (int i = 0; i < 9; i++) sR[t][i] = R[i];
#pragma unroll
        for (int i = 0; i < 9; i++) out[OFF_R + (size_t)b*216 + t*9 + i] = R[i];
        if (t >= 1) {
#pragma unroll
            for (int i = 0; i < 9; i++) {
                float id = (i==0 || i==4 || i==8) ? 1.f : 0.f;
                g_AB[b*KP + NB + (t-1)*9 + i] = R[i] - id;
            }
        }
#pragma unroll
        for (int k = 0; k < 3; k++) {
            float jr = g_Jt[t*3 + k];
#pragma unroll
            for (int l = 0; l < NB; l++)
                jr = fmaf(betas[b*NB + l], g_Jsd[t*30 + k*NB + l], jr);
            sJ[t][k] = jr;
        }
    }
    if (t < NB) g_AB[b*KP + t] = betas[b*NB + t];
    if (t == 24) {
#pragma unroll
        for (int i = NB + NP; i < KP; i++) g_AB[b*KP + i] = 0.f;
    }
    __syncthreads();

    if (t == 0) {
#pragma unroll
        for (int r = 0; r < 3; r++) {
            sG[0][r*4+0] = sR[0][r*3+0];
            sG[0][r*4+1] = sR[0][r*3+1];
            sG[0][r*4+2] = sR[0][r*3+2];
            sG[0][r*4+3] = sJ[0][r];
        }
        for (int j = 1; j < NJ; j++) {
            int p = c_parents[j];
            float rel0 = sJ[j][0] - sJ[p][0];
            float rel1 = sJ[j][1] - sJ[p][1];
            float rel2 = sJ[j][2] - sJ[p][2];
#pragma unroll
            for (int r = 0; r < 3; r++) {
                float g0 = sG[p][r*4+0], g1 = sG[p][r*4+1], g2 = sG[p][r*4+2];
#pragma unroll
                for (int cc = 0; cc < 3; cc++)
                    sG[j][r*4+cc] = g0*sR[j][0*3+cc] + g1*sR[j][1*3+cc] + g2*sR[j][2*3+cc];
                sG[j][r*4+3] = g0*rel0 + g1*rel1 + g2*rel2 + sG[p][r*4+3];
            }
        }
        g_root[b*3+0] = sG[0][3];
        g_root[b*3+1] = sG[0][7];
        g_root[b*3+2] = sG[0][11];
    }
    __syncthreads();

    if (t < NJ) {
        float j0 = sJ[t][0], j1 = sJ[t][1], j2 = sJ[t][2];
#pragma unroll
        for (int r = 0; r < 3; r++) {
            float g0 = sG[t][r*4+0], g1 = sG[t][r*4+1], g2 = sG[t][r*4+2], gt = sG[t][r*4+3];
            float* A = &g_A[((size_t)b*NJ + t)*12 + r*4];
            A[0] = g0; A[1] = g1; A[2] = g2;
            A[3] = gt - (g0*j0 + g1*j1 + g2*j2);
            out[OFF_J + (size_t)b*72 + t*3 + r] = gt - sG[0][r*4+3];
        }
    }
}

// ============================================================================
// Kernel 4: pack bf16 GEMM A fragments + tf32 skin A-mat fragments
// ============================================================================
#define PACKA_THREADS (MBLK * KA16 * 8 * 32)
#define PACKAM_THREADS (BTB * 3 * 12 * 32)
__global__ void __launch_bounds__(256) k_pack() {
    int gidx = blockIdx.x * 256 + threadIdx.x;
    if (gidx < PACKA_THREADS) {
        int idx = gidx;
        int t = idx & 31;
        int m_sub = (idx >> 5) & 7;
        int rest = idx >> 8;
        int ka = rest % KA16;
        int m_blk = rest / KA16;
        int g = t >> 2, tig = t & 3;
        int row0 = m_blk * 128 + m_sub * 16 + g;
        int k0 = ka * 16 + 2 * tig;
        const float* r0 = &g_AB[row0 * KP];
        const float* r1 = &g_AB[(row0 + 8) * KP];
        uint4 a;
        a.x = bf16x2_pack(r0[k0],     r0[k0 + 1]);
        a.y = bf16x2_pack(r1[k0],     r1[k0 + 1]);
        a.z = bf16x2_pack(r0[k0 + 8], r0[k0 + 9]);
        a.w = bf16x2_pack(r1[k0 + 8], r1[k0 + 9]);
        g_Afrag16[((size_t)(m_blk * KA16 + ka) * 8 + m_sub) * 32 + t] = a;
    } else {
        int idx = gidx - PACKA_THREADS;
        int lane = idx & 31;
        int atom = idx >> 5;
        int na = atom % 12;
        int rest = atom / 12;
        int ka = rest % 3;
        int bt = rest / 3;
        int g = lane >> 2, tig = lane & 3;
        int b = bt * 8 + g;
        int j0 = ka * 8 + tig;
        uint2 hi;
        hi.x = tf32_bits(g_A[((size_t)b * NJ + j0) * 12 + na]);
        hi.y = tf32_bits(g_A[((size_t)b * NJ + j0 + 4) * 12 + na]);
        g_Afh[idx] = hi;
    }
}

// ============================================================================
// Kernel 5: bf16 tensor-core GEMM (m16n8k16, 2 k-atoms/stage, bf16 epilogue)
// ============================================================================
__global__ void __launch_bounds__(256, 2) k_gemm() {
    __shared__ uint4 sA[2][2][8][32];
    __shared__ uint2 sB[2][2][16][32];
    int n_blk = blockIdx.x;
    int m_blk = blockIdx.y;
    int tid = threadIdx.x;
    int lane = tid & 31;
    int wid = tid >> 5;
    int wm = wid >> 1;
    int wn = wid & 1;

    const uint4* gA = g_Afrag16 + (size_t)m_blk * KA16 * 256;
    const uint2* gB = g_Bfrag16 + (size_t)n_blk * KA16 * 512;

    float4 acc[2][8];
#pragma unroll
    for (int i = 0; i < 2; i++)
#pragma unroll
        for (int j = 0; j < 8; j++) acc[i][j] = make_float4(0.f, 0.f, 0.f, 0.f);

    uint4 pa[2];
    uint2 pb0[2], pb1[2];
#pragma unroll
    for (int u = 0; u < 2; u++) {
        pa[u]  = gA[u * 256 + tid];
        pb0[u] = gB[u * 512 + tid];
        pb1[u] = gB[u * 512 + tid + 256];
    }

    int a_ms = tid >> 5;
    int b_ns0 = tid >> 5;
    int b_ns1 = 8 + (tid >> 5);

#pragma unroll
    for (int s = 0; s < KA16 / 2; s++) {
        int buf = s & 1;
#pragma unroll
        for (int u = 0; u < 2; u++) {
            sA[buf][u][a_ms][lane] = pa[u];
            sB[buf][u][b_ns0][lane] = pb0[u];
            sB[buf][u][b_ns1][lane] = pb1[u];
        }
        __syncthreads();
        if (s + 1 < KA16 / 2) {
#pragma unroll
            for (int u = 0; u < 2; u++) {
                int ka = 2 * (s + 1) + u;
                pa[u]  = gA[ka * 256 + tid];
                pb0[u] = gB[ka * 512 + tid];
                pb1[u] = gB[ka * 512 + tid + 256];
            }
        }
#pragma unroll
        for (int u = 0; u < 2; u++) {
            uint4 af[2];
            af[0] = sA[buf][u][wm * 2 + 0][lane];
            af[1] = sA[buf][u][wm * 2 + 1][lane];
            uint2 bf[8];
#pragma unroll
            for (int j = 0; j < 8; j++) bf[j] = sB[buf][u][wn * 8 + j][lane];
#pragma unroll
            for (int i = 0; i < 2; i++)
#pragma unroll
                for (int j = 0; j < 8; j++)
                    mma_bf16(acc[i][j], af[i], bf[j]);
        }
    }

    int g = lane >> 2, tig = lane & 3;
#pragma unroll
    for (int i = 0; i < 2; i++) {
        int r0 = m_blk * 128 + (wm * 2 + i) * 16 + g;
#pragma unroll
        for (int j = 0; j < 8; j++) {
            int c = n_blk * 128 + (wn * 8 + j) * 8 + tig * 2;
            *(uint32_t*)&g_vposed[(size_t)r0 * NPAD + c]       = bf16x2_pack(acc[i][j].x, acc[i][j].y);
            *(uint32_t*)&g_vposed[(size_t)(r0 + 8) * NPAD + c] = bf16x2_pack(acc[i][j].z, acc[i][j].w);
        }
    }
}

// ============================================================================
// Kernel 6: tensor-core skinning (R16: single tf32, 4 blocks/SM)
// ============================================================================
__global__ void __launch_bounds__(256, 4) k_skin_tc(const float* __restrict__ vtmpl,
                                                    float* __restrict__ out_verts) {
    __shared__ uint2 sAh[3 * 12 * 32];
    __shared__ float sP[8][385];
    __shared__ float sRoot[8][3];
    int vb = blockIdx.x;
    int bt = blockIdx.y;
    int v0 = vb * 128;
    int b0 = bt * 8;
    int tid = threadIdx.x;
    int lane = tid & 31;
    int ma = tid >> 5;

#pragma unroll
    for (int ka = 0; ka < 3; ka++)
        prefetch_l1(&g_Wfh[(((size_t)vb * 3 + ka) * 8 + ma) * 32 + lane]);

    {
        const uint2* gh = g_Afh + (size_t)bt * 1152;
#pragma unroll
        for (int r = 0; r < 5; r++) {
            int i = tid + r * 256;
            if (i < 1152) sAh[i] = gh[i];
        }
    }
#pragma unroll
    for (int k = 0; k < 12; k++) {
        int idx = tid + k * 256;
        int bi = idx / 384;
        int off = idx % 384;
        int gcol = v0 * 3 + off;
        float tpl = (gcol < NCOL) ? vtmpl[gcol] : 0.f;
        sP[bi][off] = __bfloat162float(g_vposed[(size_t)(b0 + bi) * NPAD + gcol]) + tpl;
    }
    if (tid < 24) sRoot[tid / 3][tid % 3] = g_root[(b0 + tid / 3) * 3 + tid % 3];
    __syncthreads();

    int g = lane >> 2, tig = lane & 3;

    float4 acc[12];
#pragma unroll
    for (int i = 0; i < 12; i++) acc[i] = make_float4(0.f, 0.f, 0.f, 0.f);

#pragma unroll
    for (int ka = 0; ka < 3; ka++) {
        uint4 wh = g_Wfh[(((size_t)vb * 3 + ka) * 8 + ma) * 32 + lane];
#pragma unroll
        for (int na = 0; na < 12; na++) {
            uint2 bh = sAh[(ka * 12 + na) * 32 + lane];
            mma_tf32(acc[na], wh, bh);
        }
    }

    int vl0 = ma * 16 + g;
#pragma unroll
    for (int pp = 0; pp < 4; pp++) {
        int vl = vl0 + (pp >> 1) * 8;
        int bi = 2 * tig + (pp & 1);
        int v = v0 + vl;
        if (v < NV) {
            float T[12];
#pragma unroll
            for (int na = 0; na < 12; na++) {
                float4 a = acc[na];
                T[na] = (pp == 0) ? a.x : (pp == 1) ? a.y : (pp == 2) ? a.z : a.w;
            }
            float px = sP[bi][vl * 3 + 0];
            float py = sP[bi][vl * 3 + 1];
            float pz = sP[bi][vl * 3 + 2];
            float ox = T[0]*px + T[1]*py + T[2] *pz + T[3]  - sRoot[bi][0];
            float oy = T[4]*px + T[5]*py + T[6] *pz + T[7]  - sRoot[bi][1];
            float oz = T[8]*px + T[9]*py + T[10]*pz + T[11] - sRoot[bi][2];
            size_t o = (size_t)(b0 + bi) * NCOL + (size_t)v * 3;
            out_verts[o + 0] = ox;
            out_verts[o + 1] = oy;
            out_verts[o + 2] = oz;
        }
    }
}

// ============================================================================
// Kernel 7: jfv — Jh in fp16 (R15)
// ============================================================================
__global__ void __launch_bounds__(256) k_jfv(const float* __restrict__ verts,
                                             float* __restrict__ out_jfv) {
    int b0 = blockIdx.x * 2;
    int tid = threadIdx.x;
    u64 acc2[51];
#pragma unroll
    for (int i = 0; i < 51; i++) acc2[i] = 0ull;

    const float* va_base = verts + (size_t)b0 * NCOL;
    const float* vb_base = va_base + NCOL;
    for (int v = tid; v < NV; v += 256) {
        const float* va = va_base + (size_t)v * 3;
        const float* vb = vb_base + (size_t)v * 3;
        u64 x2 = pack2(va[0], vb[0]);
        u64 y2 = pack2(va[1], vb[1]);
        u64 z2 = pack2(va[2], vb[2]);
#pragma unroll
        for (int j = 0; j < 17; j++) {
            float jr = __half2float(g_Jh16[j * NV + v]);
            u64 jr2 = pack2(jr, jr);
            acc2[j*3+0] = ffma2(jr2, x2, acc2[j*3+0]);
            acc2[j*3+1] = ffma2(jr2, y2, acc2[j*3+1]);
            acc2[j*3+2] = ffma2(jr2, z2, acc2[j*3+2]);
        }
    }

    float a[102];
#pragma unroll
    for (int i = 0; i < 51; i++) {
        float2 f = unpack2(acc2[i]);
        a[i] = f.x;
        a[51 + i] = f.y;
    }

    __shared__ float red[8][102];
    int lane = tid & 31, warp = tid >> 5;
#pragma unroll
    for (int i = 0; i < 102; i++) {
        float x = a[i];
        for (int off = 16; off; off >>= 1) x += __shfl_down_sync(0xffffffffu, x, off);
        if (lane == 0) red[warp][i] = x;
    }
    __syncthreads();
    if (tid < 102) {
        float s = 0.f;
#pragma unroll
        for (int w = 0; w < 8; w++) s += red[w][tid];
        red[0][tid] = s;
    }
    __syncthreads();
    if (tid < 102) {
        int bb = tid / 51;
        int jk = tid % 51;
        int k = jk % 3;
        float val = red[0][tid] - red[0][bb * 51 + k];
        out_jfv[(size_t)(b0 + bb) * 51 + jk] = val;
    }
}

// ============================================================================
extern "C" void kernel_launch(void* const* d_in, const int* in_sizes, int n_in,
                              void* d_out, int out_size) {
    const float* pose      = (const float*)d_in[0];
    const float* betas     = (const float*)d_in[1];
    const float* gorient   = (const float*)d_in[2];
    const float* vtmpl     = (const float*)d_in[3];
    const float* shapedirs = (const float*)d_in[4];
    const float* posedirs  = (const float*)d_in[5];
    const float* Jreg      = (const float*)d_in[6];
    const float* Jh        = (const float*)d_in[7];
    const float* wgt       = (const float*)d_in[8];
    float* out = (float*)d_out;

    k_jreg_part<<<NJ * JCH, 256>>>(Jreg, vtmpl, shapedirs);
    k_jh16<<<(17 * NV + 255) / 256, 256>>>(Jh);
    k_front<<<BFRAG_BLOCKS + (NVB * 3 * 8 * 32) / 256, 256>>>(shapedirs, posedirs, wgt);
    k_jred<<<1, 256>>>();
    k_batch<<<BATCH, 32>>>(pose, betas, gorient, out);
    k_pack<<<(PACKA_THREADS + PACKAM_THREADS + 255) / 256, 256>>>();
    k_gemm<<<dim3(NBLK, MBLK), 256>>>();
    k_skin_tc<<<dim3(NVB, BTB), 256>>>(vtmpl, out + OFF_VERTS);
    k_jfv<<<BATCH / 2, 256>>>(out + OFF_VERTS, out + OFF_F);
}